// round 7
// baseline (speedup 1.0000x reference)
#include <cuda_runtime.h>
#include <cuda_bf16.h>

#define NN 50000
#define EE 800000
#define DD 128

// ---------------- device scratch (no allocs allowed) ----------------
__device__ float4 g_h[NN * 32];      // layer buffer A (pre-scaled by norm_src)
__device__ float4 g_h2[NN * 32];     // layer buffer B (ping-pong)
__device__ int    g_deg[2 * NN];     // [0,NN)=deg_out, [NN,2NN)=deg_in
__device__ float  g_norm_src[NN];
__device__ float  g_norm_dst[NN];
__device__ int    g_row_ptr[NN + 1];
__device__ int    g_cursor[NN];
__device__ int    g_col[EE];         // src ids grouped by dst
__device__ int    g_bsum[64];

// ---------------- setup kernels ----------------
__global__ void k_degree(const int4* __restrict__ src4, const int4* __restrict__ dst4) {
    int t = blockIdx.x * blockDim.x + threadIdx.x;
    if (t < EE / 4) {
        int4 s = src4[t];
        int4 d = dst4[t];
        atomicAdd(&g_deg[s.x], 1); atomicAdd(&g_deg[s.y], 1);
        atomicAdd(&g_deg[s.z], 1); atomicAdd(&g_deg[s.w], 1);
        atomicAdd(&g_deg[NN + d.x], 1); atomicAdd(&g_deg[NN + d.y], 1);
        atomicAdd(&g_deg[NN + d.z], 1); atomicAdd(&g_deg[NN + d.w], 1);
    }
}

// scan phase 1 over deg_in (1024/block) + norms (fused)
__global__ void k_scan1n() {
    __shared__ int warp_sums[32];
    const int tid = threadIdx.x;
    int i = blockIdx.x * 1024 + tid;
    int v = 0;
    if (i < NN) {
        int dout = g_deg[i];      if (dout < 1) dout = 1;
        int din  = g_deg[NN + i];
        v = din;
        if (din < 1) din = 1;
        g_norm_src[i] = rsqrtf((float)dout);
        g_norm_dst[i] = rsqrtf((float)din);
    }
    int x = v;
    #pragma unroll
    for (int off = 1; off < 32; off <<= 1) {
        int y = __shfl_up_sync(0xffffffffu, x, off);
        if ((tid & 31) >= off) x += y;
    }
    if ((tid & 31) == 31) warp_sums[tid >> 5] = x;
    __syncthreads();
    if (tid < 32) {
        int w = warp_sums[tid];
        #pragma unroll
        for (int off = 1; off < 32; off <<= 1) {
            int y = __shfl_up_sync(0xffffffffu, w, off);
            if (tid >= off) w += y;
        }
        warp_sums[tid] = w;
    }
    __syncthreads();
    int warp_off = (tid >= 32) ? warp_sums[(tid >> 5) - 1] : 0;
    int incl = x + warp_off;
    if (i < NN) g_row_ptr[i] = incl - v;       // local exclusive
    if (tid == 1023) g_bsum[blockIdx.x] = incl;
}

// scan phase 2 (merged): each block derives its 1024-group offset from g_bsum
__global__ void k_scan3() {
    __shared__ int s_off;
    const int tid = threadIdx.x;
    const int grp = blockIdx.x >> 2;
    if (tid < 32) {
        int a = (tid < grp)      ? g_bsum[tid]      : 0;
        int b = (tid + 32 < grp) ? g_bsum[tid + 32] : 0;
        int s = a + b;
        #pragma unroll
        for (int off = 16; off > 0; off >>= 1)
            s += __shfl_down_sync(0xffffffffu, s, off);
        if (tid == 0) s_off = s;
    }
    __syncthreads();
    int i = blockIdx.x * 256 + tid;
    if (i < NN) {
        int val = g_row_ptr[i] + s_off;
        g_row_ptr[i] = val;
        g_cursor[i]  = val;
    }
    if (i == 0) g_row_ptr[NN] = EE;
}

__global__ void k_fill(const int4* __restrict__ src4, const int4* __restrict__ dst4) {
    int t = blockIdx.x * blockDim.x + threadIdx.x;
    if (t < EE / 4) {
        int4 s = src4[t];
        int4 d = dst4[t];
        g_col[atomicAdd(&g_cursor[d.x], 1)] = s.x;
        g_col[atomicAdd(&g_cursor[d.y], 1)] = s.y;
        g_col[atomicAdd(&g_cursor[d.z], 1)] = s.z;
        g_col[atomicAdd(&g_cursor[d.w], 1)] = s.w;
    }
}

// h0 = emb[batch] * norm_src
__global__ void k_h0(const int* __restrict__ batch, const float4* __restrict__ emb) {
    int idx = blockIdx.x * blockDim.x + threadIdx.x;
    if (idx >= NN * 32) return;
    int i = idx >> 5, q = idx & 31;
    float ns = g_norm_src[i];
    float4 v = emb[(size_t)batch[i] * 32 + q];
    v.x *= ns; v.y *= ns; v.z *= ns; v.w *= ns;
    g_h[idx] = v;
}

// ---------------- fused layer: SpMM (pull) + TF32 GEMM + relu + rowscale ----------------
__device__ __forceinline__ unsigned f2tf(float f) {
    unsigned u;
    asm("cvt.rna.tf32.f32 %0, %1;" : "=r"(u) : "f"(f));
    return u;
}

#define AS2 132
#define BS_STRIDE 136
#define FUSED_SMEM ((128 * AS2 + 64 * BS_STRIDE) * 4)   // 102400 B

__global__ __launch_bounds__(256, 2) void k_layer(
    const float4* __restrict__ hin,
    const float4* __restrict__ W4, const float* __restrict__ bias,
    const float* __restrict__ rowscale, float2* __restrict__ out)
{
    extern __shared__ unsigned smem[];
    unsigned* As = smem;                  // [128][132] tf32
    unsigned* Bs = smem + 128 * AS2;      // [64][136]  tf32

    const int tid  = threadIdx.x;
    const int wid  = tid >> 5;
    const int lane = tid & 31;
    const int row0 = blockIdx.x * 128;

    // ---- phase 1: aggregate 16 dst rows per warp straight into As (tf32) ----
    #pragma unroll 1
    for (int j = 0; j < 16; j++) {
        int lr = wid + j * 8;             // 0..127
        int r  = row0 + lr;
        float4 acc = make_float4(0.f, 0.f, 0.f, 0.f);
        if (r < NN) {
            int beg = g_row_ptr[r];
            int end = g_row_ptr[r + 1];
            for (int j0 = beg; j0 < end; j0 += 32) {
                int c = 0;
                if (j0 + lane < end) c = g_col[j0 + lane];
                int n = end - j0; if (n > 32) n = 32;
                int t = 0;
                for (; t + 3 < n; t += 4) {
                    int s0 = __shfl_sync(0xffffffffu, c, t);
                    int s1 = __shfl_sync(0xffffffffu, c, t + 1);
                    int s2 = __shfl_sync(0xffffffffu, c, t + 2);
                    int s3 = __shfl_sync(0xffffffffu, c, t + 3);
                    float4 v0 = hin[s0 * 32 + lane];
                    float4 v1 = hin[s1 * 32 + lane];
                    float4 v2 = hin[s2 * 32 + lane];
                    float4 v3 = hin[s3 * 32 + lane];
                    acc.x += v0.x + v1.x + v2.x + v3.x;
                    acc.y += v0.y + v1.y + v2.y + v3.y;
                    acc.z += v0.z + v1.z + v2.z + v3.z;
                    acc.w += v0.w + v1.w + v2.w + v3.w;
                }
                for (; t < n; t++) {
                    int s = __shfl_sync(0xffffffffu, c, t);
                    float4 v = hin[s * 32 + lane];
                    acc.x += v.x; acc.y += v.y; acc.z += v.z; acc.w += v.w;
                }
            }
            float nd = g_norm_dst[r];
            acc.x *= nd; acc.y *= nd; acc.z *= nd; acc.w *= nd;
        }
        uint4 tt = make_uint4(f2tf(acc.x), f2tf(acc.y), f2tf(acc.z), f2tf(acc.w));
        *(uint4*)&As[lr * AS2 + lane * 4] = tt;
    }
    __syncthreads();

    // ---- phase 2: 128x128x128 tf32 MMA against W ----
    const int g = lane >> 2;       // 0..7
    const int c = lane & 3;        // 0..3
    const int wm = (wid & 3) * 32;
    const int wn = (wid >> 2) * 64;

    float acc[2][8][4];
    #pragma unroll
    for (int i = 0; i < 2; i++)
        #pragma unroll
        for (int j = 0; j < 8; j++)
            #pragma unroll
            for (int k = 0; k < 4; k++) acc[i][j][k] = 0.f;

    for (int k0 = 0; k0 < 128; k0 += 64) {
        #pragma unroll
        for (int l = 0; l < 8; l++) {
            int idx = l * 256 + tid;
            int k = idx >> 5;            // 0..63
            int nq = idx & 31;
            float4 v = __ldg(&W4[(size_t)(k0 + k) * 32 + nq]);
            uint4 t = make_uint4(f2tf(v.x), f2tf(v.y), f2tf(v.z), f2tf(v.w));
            *(uint4*)&Bs[k * BS_STRIDE + nq * 4] = t;
        }
        __syncthreads();

        #pragma unroll
        for (int kk = 0; kk < 64; kk += 8) {
            unsigned a[2][4];
            #pragma unroll
            for (int mt = 0; mt < 2; mt++) {
                int r = wm + mt * 16 + g;
                a[mt][0] = As[r * AS2 + k0 + kk + c];
                a[mt][1] = As[(r + 8) * AS2 + k0 + kk + c];
                a[mt][2] = As[r * AS2 + k0 + kk + c + 4];
                a[mt][3] = As[(r + 8) * AS2 + k0 + kk + c + 4];
            }
            #pragma unroll
            for (int nt = 0; nt < 8; nt++) {
                unsigned b0 = Bs[(kk + c) * BS_STRIDE + wn + nt * 8 + g];
                unsigned b1 = Bs[(kk + c + 4) * BS_STRIDE + wn + nt * 8 + g];
                #pragma unroll
                for (int mt = 0; mt < 2; mt++) {
                    asm volatile(
                        "mma.sync.aligned.m16n8k8.row.col.f32.tf32.tf32.f32 "
                        "{%0,%1,%2,%3}, {%4,%5,%6,%7}, {%8,%9}, {%0,%1,%2,%3};\n"
                        : "+f"(acc[mt][nt][0]), "+f"(acc[mt][nt][1]),
                          "+f"(acc[mt][nt][2]), "+f"(acc[mt][nt][3])
                        : "r"(a[mt][0]), "r"(a[mt][1]), "r"(a[mt][2]), "r"(a[mt][3]),
                          "r"(b0), "r"(b1));
                }
            }
        }
        __syncthreads();
    }

    // ---- epilogue: bias + relu (+ rowscale = norm_src for next layer) ----
    const int c2 = c * 2;
    #pragma unroll
    for (int nt = 0; nt < 8; nt++) {
        int col = wn + nt * 8 + c2;
        float bi0 = bias[col], bi1 = bias[col + 1];
        #pragma unroll
        for (int mt = 0; mt < 2; mt++) {
            int r = row0 + wm + mt * 16 + g;
            if (r < NN) {
                float rs = rowscale ? rowscale[r] : 1.0f;
                float2 o;
                o.x = fmaxf(acc[mt][nt][0] + bi0, 0.f) * rs;
                o.y = fmaxf(acc[mt][nt][1] + bi1, 0.f) * rs;
                out[r * 64 + (col >> 1)] = o;
            }
            int r2 = r + 8;
            if (r2 < NN) {
                float rs = rowscale ? rowscale[r2] : 1.0f;
                float2 o;
                o.x = fmaxf(acc[mt][nt][2] + bi0, 0.f) * rs;
                o.y = fmaxf(acc[mt][nt][3] + bi1, 0.f) * rs;
                out[r2 * 64 + (col >> 1)] = o;
            }
        }
    }
}

// ---------------- launch (single stream) ----------------
extern "C" void kernel_launch(void* const* d_in, const int* in_sizes, int n_in,
                              void* d_out, int out_size)
{
    const int*   batch = (const int*)d_in[0];
    const int*   src   = (const int*)d_in[1];
    const int*   dst   = (const int*)d_in[2];
    const float* emb   = (const float*)d_in[3];
    const float* W1    = (const float*)d_in[4];
    const float* b1    = (const float*)d_in[5];
    const float* W2    = (const float*)d_in[6];
    const float* b2    = (const float*)d_in[7];
    const float* W3    = (const float*)d_in[8];
    const float* b3    = (const float*)d_in[9];
    float* outp = (float*)d_out;

    float4* hA;  cudaGetSymbolAddress((void**)&hA, g_h);
    float4* hB;  cudaGetSymbolAddress((void**)&hB, g_h2);
    int* degp;   cudaGetSymbolAddress((void**)&degp, g_deg);
    float* nsrc; cudaGetSymbolAddress((void**)&nsrc, g_norm_src);

    cudaFuncSetAttribute(k_layer, cudaFuncAttributeMaxDynamicSharedMemorySize,
                         FUSED_SMEM);

    const int scan_blocks = (NN + 1023) / 1024;   // 49

    cudaMemsetAsync(degp, 0, 2 * NN * sizeof(int), 0);
    k_degree<<<(EE / 4 + 255) / 256, 256>>>((const int4*)src, (const int4*)dst);
    k_scan1n<<<scan_blocks, 1024>>>();
    k_h0<<<(NN * 32 + 255) / 256, 256>>>(batch, (const float4*)emb);
    k_scan3<<<(NN + 255) / 256, 256>>>();
    k_fill<<<(EE / 4 + 255) / 256, 256>>>((const int4*)src, (const int4*)dst);

    const int grid = (NN + 127) / 128;            // 391

    // ping-pong: hA -> hB -> hA -> d_out
    k_layer<<<grid, 256, FUSED_SMEM>>>(hA, (const float4*)W1, b1, nsrc, (float2*)hB);
    k_layer<<<grid, 256, FUSED_SMEM>>>(hB, (const float4*)W2, b2, nsrc, (float2*)hA);
    k_layer<<<grid, 256, FUSED_SMEM>>>(hA, (const float4*)W3, b3, nullptr, (float2*)outp);
}

// round 8
// speedup vs baseline: 1.4708x; 1.4708x over previous
#include <cuda_runtime.h>
#include <cuda_bf16.h>

#define NN 50000
#define EE 800000
#define DD 128

// ---------------- device scratch (no allocs allowed) ----------------
__device__ float4 g_h[NN * 32];      // current layer input, pre-scaled by norm_src
__device__ float4 g_agg[NN * 32];    // SpMM output (already * norm_dst)
__device__ int    g_deg[2 * NN];     // [0,NN)=deg_out, [NN,2NN)=deg_in
__device__ float  g_norm_src[NN];
__device__ float  g_norm_dst[NN];
__device__ int    g_row_ptr[NN + 1];
__device__ int    g_cursor[NN];
__device__ int    g_col[EE];         // src ids grouped by dst
__device__ int    g_bsum[64];

// ---------------- setup kernels ----------------
__global__ void k_degree(const int4* __restrict__ src4, const int4* __restrict__ dst4) {
    int t = blockIdx.x * blockDim.x + threadIdx.x;
    if (t < EE / 4) {
        int4 s = src4[t];
        int4 d = dst4[t];
        atomicAdd(&g_deg[s.x], 1); atomicAdd(&g_deg[s.y], 1);
        atomicAdd(&g_deg[s.z], 1); atomicAdd(&g_deg[s.w], 1);
        atomicAdd(&g_deg[NN + d.x], 1); atomicAdd(&g_deg[NN + d.y], 1);
        atomicAdd(&g_deg[NN + d.z], 1); atomicAdd(&g_deg[NN + d.w], 1);
    }
}

// scan phase 1 over deg_in (1024/block) + norms (fused)
__global__ void k_scan1n() {
    __shared__ int warp_sums[32];
    const int tid = threadIdx.x;
    int i = blockIdx.x * 1024 + tid;
    int v = 0;
    if (i < NN) {
        int dout = g_deg[i];      if (dout < 1) dout = 1;
        int din  = g_deg[NN + i];
        v = din;
        if (din < 1) din = 1;
        g_norm_src[i] = rsqrtf((float)dout);
        g_norm_dst[i] = rsqrtf((float)din);
    }
    int x = v;
    #pragma unroll
    for (int off = 1; off < 32; off <<= 1) {
        int y = __shfl_up_sync(0xffffffffu, x, off);
        if ((tid & 31) >= off) x += y;
    }
    if ((tid & 31) == 31) warp_sums[tid >> 5] = x;
    __syncthreads();
    if (tid < 32) {
        int w = warp_sums[tid];
        #pragma unroll
        for (int off = 1; off < 32; off <<= 1) {
            int y = __shfl_up_sync(0xffffffffu, w, off);
            if (tid >= off) w += y;
        }
        warp_sums[tid] = w;
    }
    __syncthreads();
    int warp_off = (tid >= 32) ? warp_sums[(tid >> 5) - 1] : 0;
    int incl = x + warp_off;
    if (i < NN) g_row_ptr[i] = incl - v;       // local exclusive
    if (tid == 1023) g_bsum[blockIdx.x] = incl;
}

// scan phase 2 (merged): each block derives its 1024-group offset from g_bsum
__global__ void k_scan3() {
    __shared__ int s_off;
    const int tid = threadIdx.x;
    const int grp = blockIdx.x >> 2;
    if (tid < 32) {
        int a = (tid < grp)      ? g_bsum[tid]      : 0;
        int b = (tid + 32 < grp) ? g_bsum[tid + 32] : 0;
        int s = a + b;
        #pragma unroll
        for (int off = 16; off > 0; off >>= 1)
            s += __shfl_down_sync(0xffffffffu, s, off);
        if (tid == 0) s_off = s;
    }
    __syncthreads();
    int i = blockIdx.x * 256 + tid;
    if (i < NN) {
        int val = g_row_ptr[i] + s_off;
        g_row_ptr[i] = val;
        g_cursor[i]  = val;
    }
    if (i == 0) g_row_ptr[NN] = EE;
}

__global__ void k_fill(const int4* __restrict__ src4, const int4* __restrict__ dst4) {
    int t = blockIdx.x * blockDim.x + threadIdx.x;
    if (t < EE / 4) {
        int4 s = src4[t];
        int4 d = dst4[t];
        g_col[atomicAdd(&g_cursor[d.x], 1)] = s.x;
        g_col[atomicAdd(&g_cursor[d.y], 1)] = s.y;
        g_col[atomicAdd(&g_cursor[d.z], 1)] = s.z;
        g_col[atomicAdd(&g_cursor[d.w], 1)] = s.w;
    }
}

// h0 = emb[batch] * norm_src   (requires norms; runs after k_scan1n)
__global__ void k_h0(const int* __restrict__ batch, const float4* __restrict__ emb) {
    int idx = blockIdx.x * blockDim.x + threadIdx.x;
    if (idx >= NN * 32) return;
    int i = idx >> 5, q = idx & 31;
    float ns = g_norm_src[i];
    float4 v = emb[(size_t)batch[i] * 32 + q];
    v.x *= ns; v.y *= ns; v.z *= ns; v.w *= ns;
    g_h[idx] = v;
}

// ---------------- SpMM: pull-style, warp per dst node (plain adds) ----------------
__global__ void k_spmm() {
    int warp = (blockIdx.x * blockDim.x + threadIdx.x) >> 5;
    int lane = threadIdx.x & 31;
    if (warp >= NN) return;
    int beg = g_row_ptr[warp];
    int end = g_row_ptr[warp + 1];
    float4 acc = make_float4(0.f, 0.f, 0.f, 0.f);
    for (int j0 = beg; j0 < end; j0 += 32) {
        int c = 0;
        if (j0 + lane < end) c = g_col[j0 + lane];
        int n = end - j0; if (n > 32) n = 32;
        int t = 0;
        for (; t + 3 < n; t += 4) {
            int s0 = __shfl_sync(0xffffffffu, c, t);
            int s1 = __shfl_sync(0xffffffffu, c, t + 1);
            int s2 = __shfl_sync(0xffffffffu, c, t + 2);
            int s3 = __shfl_sync(0xffffffffu, c, t + 3);
            float4 v0 = g_h[s0 * 32 + lane];
            float4 v1 = g_h[s1 * 32 + lane];
            float4 v2 = g_h[s2 * 32 + lane];
            float4 v3 = g_h[s3 * 32 + lane];
            acc.x += v0.x + v1.x + v2.x + v3.x;
            acc.y += v0.y + v1.y + v2.y + v3.y;
            acc.z += v0.z + v1.z + v2.z + v3.z;
            acc.w += v0.w + v1.w + v2.w + v3.w;
        }
        for (; t < n; t++) {
            int s = __shfl_sync(0xffffffffu, c, t);
            float4 v = g_h[s * 32 + lane];
            acc.x += v.x; acc.y += v.y; acc.z += v.z; acc.w += v.w;
        }
    }
    float nd = g_norm_dst[warp];
    acc.x *= nd; acc.y *= nd; acc.z *= nd; acc.w *= nd;
    g_agg[warp * 32 + lane] = acc;
}

// ---------------- TF32 tensor-core GEMM: out = relu(A @ W + b) [* rowscale] ----------------
__device__ __forceinline__ unsigned f2tf(float f) {
    unsigned u;
    asm("cvt.rna.tf32.f32 %0, %1;" : "=r"(u) : "f"(f));
    return u;
}

#define AS_STRIDE 68
#define BS_STRIDE 136
#define GEMM_SMEM ((128 * AS_STRIDE + 64 * BS_STRIDE) * 4)

__global__ __launch_bounds__(256, 2) void k_gemm_tf32(
    const float4* __restrict__ A, const float4* __restrict__ W4,
    const float* __restrict__ bias, const float* __restrict__ rowscale,
    float2* __restrict__ out, int M)
{
    extern __shared__ unsigned smem[];
    unsigned* As = smem;                       // [128][68]
    unsigned* Bs = smem + 128 * AS_STRIDE;     // [64][136]

    const int tid  = threadIdx.x;
    const int wid  = tid >> 5;
    const int lane = tid & 31;
    const int g = lane >> 2;       // 0..7
    const int c = lane & 3;        // 0..3
    const int wm = (wid & 3) * 32;
    const int wn = (wid >> 2) * 64;
    const int row0 = blockIdx.x * 128;

    float acc[2][8][4];
    #pragma unroll
    for (int i = 0; i < 2; i++)
        #pragma unroll
        for (int j = 0; j < 8; j++)
            #pragma unroll
            for (int k = 0; k < 4; k++) acc[i][j][k] = 0.f;

    for (int k0 = 0; k0 < 128; k0 += 64) {
        #pragma unroll
        for (int l = 0; l < 8; l++) {
            int idx = l * 256 + tid;
            int r = idx >> 4;
            int q = idx & 15;
            float4 v = (row0 + r < M) ? A[(row0 + r) * 32 + (k0 >> 2) + q]
                                      : make_float4(0.f, 0.f, 0.f, 0.f);
            uint4 t = make_uint4(f2tf(v.x), f2tf(v.y), f2tf(v.z), f2tf(v.w));
            *(uint4*)&As[r * AS_STRIDE + q * 4] = t;
        }
        #pragma unroll
        for (int l = 0; l < 8; l++) {
            int idx = l * 256 + tid;
            int k = idx >> 5;
            int nq = idx & 31;
            float4 v = __ldg(&W4[(size_t)(k0 + k) * 32 + nq]);
            uint4 t = make_uint4(f2tf(v.x), f2tf(v.y), f2tf(v.z), f2tf(v.w));
            *(uint4*)&Bs[k * BS_STRIDE + nq * 4] = t;
        }
        __syncthreads();

        #pragma unroll
        for (int kk = 0; kk < 64; kk += 8) {
            unsigned a[2][4];
            #pragma unroll
            for (int mt = 0; mt < 2; mt++) {
                int r = wm + mt * 16 + g;
                a[mt][0] = As[r * AS_STRIDE + kk + c];
                a[mt][1] = As[(r + 8) * AS_STRIDE + kk + c];
                a[mt][2] = As[r * AS_STRIDE + kk + c + 4];
                a[mt][3] = As[(r + 8) * AS_STRIDE + kk + c + 4];
            }
            #pragma unroll
            for (int nt = 0; nt < 8; nt++) {
                unsigned b0 = Bs[(kk + c) * BS_STRIDE + wn + nt * 8 + g];
                unsigned b1 = Bs[(kk + c + 4) * BS_STRIDE + wn + nt * 8 + g];
                #pragma unroll
                for (int mt = 0; mt < 2; mt++) {
                    asm volatile(
                        "mma.sync.aligned.m16n8k8.row.col.f32.tf32.tf32.f32 "
                        "{%0,%1,%2,%3}, {%4,%5,%6,%7}, {%8,%9}, {%0,%1,%2,%3};\n"
                        : "+f"(acc[mt][nt][0]), "+f"(acc[mt][nt][1]),
                          "+f"(acc[mt][nt][2]), "+f"(acc[mt][nt][3])
                        : "r"(a[mt][0]), "r"(a[mt][1]), "r"(a[mt][2]), "r"(a[mt][3]),
                          "r"(b0), "r"(b1));
                }
            }
        }
        __syncthreads();
    }

    const int c2 = c * 2;
    #pragma unroll
    for (int nt = 0; nt < 8; nt++) {
        int col = wn + nt * 8 + c2;
        float bi0 = bias[col], bi1 = bias[col + 1];
        #pragma unroll
        for (int mt = 0; mt < 2; mt++) {
            int r = row0 + wm + mt * 16 + g;
            if (r < M) {
                float rs = rowscale ? rowscale[r] : 1.0f;
                float2 o;
                o.x = fmaxf(acc[mt][nt][0] + bi0, 0.f) * rs;
                o.y = fmaxf(acc[mt][nt][1] + bi1, 0.f) * rs;
                out[r * 64 + (col >> 1)] = o;
            }
            int r2 = r + 8;
            if (r2 < M) {
                float rs = rowscale ? rowscale[r2] : 1.0f;
                float2 o;
                o.x = fmaxf(acc[mt][nt][2] + bi0, 0.f) * rs;
                o.y = fmaxf(acc[mt][nt][3] + bi1, 0.f) * rs;
                out[r2 * 64 + (col >> 1)] = o;
            }
        }
    }
}

// ---------------- launch (single stream) ----------------
extern "C" void kernel_launch(void* const* d_in, const int* in_sizes, int n_in,
                              void* d_out, int out_size)
{
    const int*   batch = (const int*)d_in[0];
    const int*   src   = (const int*)d_in[1];
    const int*   dst   = (const int*)d_in[2];
    const float* emb   = (const float*)d_in[3];
    const float* W1    = (const float*)d_in[4];
    const float* b1    = (const float*)d_in[5];
    const float* W2    = (const float*)d_in[6];
    const float* b2    = (const float*)d_in[7];
    const float* W3    = (const float*)d_in[8];
    const float* b3    = (const float*)d_in[9];
    float* outp = (float*)d_out;

    float4* hbuf;   cudaGetSymbolAddress((void**)&hbuf, g_h);
    float4* aggbuf; cudaGetSymbolAddress((void**)&aggbuf, g_agg);
    int* degp;      cudaGetSymbolAddress((void**)&degp, g_deg);
    float* nsrc;    cudaGetSymbolAddress((void**)&nsrc, g_norm_src);

    cudaFuncSetAttribute(k_gemm_tf32, cudaFuncAttributeMaxDynamicSharedMemorySize,
                         GEMM_SMEM);

    const int scan_blocks = (NN + 1023) / 1024;   // 49

    cudaMemsetAsync(degp, 0, 2 * NN * sizeof(int), 0);
    k_degree<<<(EE / 4 + 255) / 256, 256>>>((const int4*)src, (const int4*)dst);
    k_scan1n<<<scan_blocks, 1024>>>();
    k_h0<<<(NN * 32 + 255) / 256, 256>>>(batch, (const float4*)emb);
    k_scan3<<<(NN + 255) / 256, 256>>>();
    k_fill<<<(EE / 4 + 255) / 256, 256>>>((const int4*)src, (const int4*)dst);

    const int gemm_grid = (NN + 127) / 128;       // 391
    const int spmm_grid = (NN + 7) / 8;

    // layer 1
    k_spmm<<<spmm_grid, 256>>>();
    k_gemm_tf32<<<gemm_grid, 256, GEMM_SMEM>>>(aggbuf, (const float4*)W1, b1, nsrc,
                                               (float2*)hbuf, NN);
    // layer 2
    k_spmm<<<spmm_grid, 256>>>();
    k_gemm_tf32<<<gemm_grid, 256, GEMM_SMEM>>>(aggbuf, (const float4*)W2, b2, nsrc,
                                               (float2*)hbuf, NN);
    // layer 3 -> d_out
    k_spmm<<<spmm_grid, 256>>>();
    k_gemm_tf32<<<gemm_grid, 256, GEMM_SMEM>>>(aggbuf, (const float4*)W3, b3, nullptr,
                                               (float2*)outp, NN);
}

// round 9
// speedup vs baseline: 1.6563x; 1.1262x over previous
#include <cuda_runtime.h>
#include <cuda_fp16.h>

#define NN 50000
#define EE 800000
#define DD 128

// ---------------- device scratch (no allocs allowed) ----------------
__device__ __half2 g_hh[NN * 64];    // current layer input, fp16, pre-scaled by norm_src
__device__ float4  g_agg[NN * 32];   // SpMM output, fp32 (already * norm_dst)
__device__ int     g_deg[2 * NN];    // [0,NN)=deg_out, [NN,2NN)=deg_in
__device__ float   g_norm_src[NN];
__device__ float   g_norm_dst[NN];
__device__ int     g_row_ptr[NN + 1];
__device__ int     g_cursor[NN];
__device__ int     g_col[EE];        // src ids grouped by dst
__device__ int     g_bsum[64];

// ---------------- setup kernels ----------------
__global__ void k_degree(const int4* __restrict__ src4, const int4* __restrict__ dst4) {
    int t = blockIdx.x * blockDim.x + threadIdx.x;
    if (t < EE / 4) {
        int4 s = src4[t];
        int4 d = dst4[t];
        atomicAdd(&g_deg[s.x], 1); atomicAdd(&g_deg[s.y], 1);
        atomicAdd(&g_deg[s.z], 1); atomicAdd(&g_deg[s.w], 1);
        atomicAdd(&g_deg[NN + d.x], 1); atomicAdd(&g_deg[NN + d.y], 1);
        atomicAdd(&g_deg[NN + d.z], 1); atomicAdd(&g_deg[NN + d.w], 1);
    }
}

// scan phase 1 over deg_in (1024/block) + norms (fused)
__global__ void k_scan1n() {
    __shared__ int warp_sums[32];
    const int tid = threadIdx.x;
    int i = blockIdx.x * 1024 + tid;
    int v = 0;
    if (i < NN) {
        int dout = g_deg[i];      if (dout < 1) dout = 1;
        int din  = g_deg[NN + i];
        v = din;
        if (din < 1) din = 1;
        g_norm_src[i] = rsqrtf((float)dout);
        g_norm_dst[i] = rsqrtf((float)din);
    }
    int x = v;
    #pragma unroll
    for (int off = 1; off < 32; off <<= 1) {
        int y = __shfl_up_sync(0xffffffffu, x, off);
        if ((tid & 31) >= off) x += y;
    }
    if ((tid & 31) == 31) warp_sums[tid >> 5] = x;
    __syncthreads();
    if (tid < 32) {
        int w = warp_sums[tid];
        #pragma unroll
        for (int off = 1; off < 32; off <<= 1) {
            int y = __shfl_up_sync(0xffffffffu, w, off);
            if (tid >= off) w += y;
        }
        warp_sums[tid] = w;
    }
    __syncthreads();
    int warp_off = (tid >= 32) ? warp_sums[(tid >> 5) - 1] : 0;
    int incl = x + warp_off;
    if (i < NN) g_row_ptr[i] = incl - v;       // local exclusive
    if (tid == 1023) g_bsum[blockIdx.x] = incl;
}

// scan phase 2 (merged): each block derives its 1024-group offset from g_bsum
__global__ void k_scan3() {
    __shared__ int s_off;
    const int tid = threadIdx.x;
    const int grp = blockIdx.x >> 2;
    if (tid < 32) {
        int a = (tid < grp)      ? g_bsum[tid]      : 0;
        int b = (tid + 32 < grp) ? g_bsum[tid + 32] : 0;
        int s = a + b;
        #pragma unroll
        for (int off = 16; off > 0; off >>= 1)
            s += __shfl_down_sync(0xffffffffu, s, off);
        if (tid == 0) s_off = s;
    }
    __syncthreads();
    int i = blockIdx.x * 256 + tid;
    if (i < NN) {
        int val = g_row_ptr[i] + s_off;
        g_row_ptr[i] = val;
        g_cursor[i]  = val;
    }
    if (i == 0) g_row_ptr[NN] = EE;
}

__global__ void k_fill(const int4* __restrict__ src4, const int4* __restrict__ dst4) {
    int t = blockIdx.x * blockDim.x + threadIdx.x;
    if (t < EE / 4) {
        int4 s = src4[t];
        int4 d = dst4[t];
        g_col[atomicAdd(&g_cursor[d.x], 1)] = s.x;
        g_col[atomicAdd(&g_cursor[d.y], 1)] = s.y;
        g_col[atomicAdd(&g_cursor[d.z], 1)] = s.z;
        g_col[atomicAdd(&g_cursor[d.w], 1)] = s.w;
    }
}

// h0 = half(emb[batch] * norm_src)   (requires norms; runs after k_scan1n)
__global__ void k_h0(const int* __restrict__ batch, const float4* __restrict__ emb) {
    int idx = blockIdx.x * blockDim.x + threadIdx.x;
    if (idx >= NN * 32) return;
    int i = idx >> 5, q = idx & 31;
    float ns = g_norm_src[i];
    float4 v = emb[(size_t)batch[i] * 32 + q];
    __half2 p0 = __floats2half2_rn(v.x * ns, v.y * ns);
    __half2 p1 = __floats2half2_rn(v.z * ns, v.w * ns);
    uint2 o = make_uint2(*(unsigned*)&p0, *(unsigned*)&p1);
    ((uint2*)g_hh)[idx] = o;
}

// ---------------- SpMM: pull-style, warp per dst node, fp16 gather / fp32 acc ----------------
__global__ void k_spmm() {
    int warp = (blockIdx.x * blockDim.x + threadIdx.x) >> 5;
    int lane = threadIdx.x & 31;
    if (warp >= NN) return;
    const uint2* hp = (const uint2*)g_hh;      // row stride = 32 uint2 (128 halves)
    int beg = g_row_ptr[warp];
    int end = g_row_ptr[warp + 1];
    float4 acc = make_float4(0.f, 0.f, 0.f, 0.f);
    for (int j0 = beg; j0 < end; j0 += 32) {
        int c = 0;
        if (j0 + lane < end) c = g_col[j0 + lane];
        int n = end - j0; if (n > 32) n = 32;
        int t = 0;
        for (; t + 3 < n; t += 4) {
            int s0 = __shfl_sync(0xffffffffu, c, t);
            int s1 = __shfl_sync(0xffffffffu, c, t + 1);
            int s2 = __shfl_sync(0xffffffffu, c, t + 2);
            int s3 = __shfl_sync(0xffffffffu, c, t + 3);
            uint2 u0 = hp[s0 * 32 + lane];
            uint2 u1 = hp[s1 * 32 + lane];
            uint2 u2 = hp[s2 * 32 + lane];
            uint2 u3 = hp[s3 * 32 + lane];
            float2 a0 = __half22float2(*(__half2*)&u0.x);
            float2 b0 = __half22float2(*(__half2*)&u0.y);
            float2 a1 = __half22float2(*(__half2*)&u1.x);
            float2 b1 = __half22float2(*(__half2*)&u1.y);
            float2 a2 = __half22float2(*(__half2*)&u2.x);
            float2 b2 = __half22float2(*(__half2*)&u2.y);
            float2 a3 = __half22float2(*(__half2*)&u3.x);
            float2 b3 = __half22float2(*(__half2*)&u3.y);
            acc.x += a0.x + a1.x + a2.x + a3.x;
            acc.y += a0.y + a1.y + a2.y + a3.y;
            acc.z += b0.x + b1.x + b2.x + b3.x;
            acc.w += b0.y + b1.y + b2.y + b3.y;
        }
        for (; t < n; t++) {
            int s = __shfl_sync(0xffffffffu, c, t);
            uint2 u = hp[s * 32 + lane];
            float2 a = __half22float2(*(__half2*)&u.x);
            float2 b = __half22float2(*(__half2*)&u.y);
            acc.x += a.x; acc.y += a.y; acc.z += b.x; acc.w += b.y;
        }
    }
    float nd = g_norm_dst[warp];
    acc.x *= nd; acc.y *= nd; acc.z *= nd; acc.w *= nd;
    // lane covers columns [4*lane, 4*lane+4)  -> float4 slot 'lane' of row
    g_agg[warp * 32 + lane] = acc;
}

// ---------------- TF32 tensor-core GEMM: out = relu(A @ W + b) [* rowscale] ----------------
__device__ __forceinline__ unsigned f2tf(float f) {
    unsigned u;
    asm("cvt.rna.tf32.f32 %0, %1;" : "=r"(u) : "f"(f));
    return u;
}

#define AS_STRIDE 68
#define BS_STRIDE 136
#define GEMM_SMEM ((128 * AS_STRIDE + 64 * BS_STRIDE) * 4)

template <bool HALF_OUT>
__global__ __launch_bounds__(256, 2) void k_gemm_tf32(
    const float4* __restrict__ A, const float4* __restrict__ W4,
    const float* __restrict__ bias, const float* __restrict__ rowscale,
    void* __restrict__ outp, int M)
{
    extern __shared__ unsigned smem[];
    unsigned* As = smem;                       // [128][68]
    unsigned* Bs = smem + 128 * AS_STRIDE;     // [64][136]

    const int tid  = threadIdx.x;
    const int wid  = tid >> 5;
    const int lane = tid & 31;
    const int g = lane >> 2;       // 0..7
    const int c = lane & 3;        // 0..3
    const int wm = (wid & 3) * 32;
    const int wn = (wid >> 2) * 64;
    const int row0 = blockIdx.x * 128;

    float acc[2][8][4];
    #pragma unroll
    for (int i = 0; i < 2; i++)
        #pragma unroll
        for (int j = 0; j < 8; j++)
            #pragma unroll
            for (int k = 0; k < 4; k++) acc[i][j][k] = 0.f;

    for (int k0 = 0; k0 < 128; k0 += 64) {
        #pragma unroll
        for (int l = 0; l < 8; l++) {
            int idx = l * 256 + tid;
            int r = idx >> 4;
            int q = idx & 15;
            float4 v = (row0 + r < M) ? A[(row0 + r) * 32 + (k0 >> 2) + q]
                                      : make_float4(0.f, 0.f, 0.f, 0.f);
            uint4 t = make_uint4(f2tf(v.x), f2tf(v.y), f2tf(v.z), f2tf(v.w));
            *(uint4*)&As[r * AS_STRIDE + q * 4] = t;
        }
        #pragma unroll
        for (int l = 0; l < 8; l++) {
            int idx = l * 256 + tid;
            int k = idx >> 5;
            int nq = idx & 31;
            float4 v = __ldg(&W4[(size_t)(k0 + k) * 32 + nq]);
            uint4 t = make_uint4(f2tf(v.x), f2tf(v.y), f2tf(v.z), f2tf(v.w));
            *(uint4*)&Bs[k * BS_STRIDE + nq * 4] = t;
        }
        __syncthreads();

        #pragma unroll
        for (int kk = 0; kk < 64; kk += 8) {
            unsigned a[2][4];
            #pragma unroll
            for (int mt = 0; mt < 2; mt++) {
                int r = wm + mt * 16 + g;
                a[mt][0] = As[r * AS_STRIDE + kk + c];
                a[mt][1] = As[(r + 8) * AS_STRIDE + kk + c];
                a[mt][2] = As[r * AS_STRIDE + kk + c + 4];
                a[mt][3] = As[(r + 8) * AS_STRIDE + kk + c + 4];
            }
            #pragma unroll
            for (int nt = 0; nt < 8; nt++) {
                unsigned b0 = Bs[(kk + c) * BS_STRIDE + wn + nt * 8 + g];
                unsigned b1 = Bs[(kk + c + 4) * BS_STRIDE + wn + nt * 8 + g];
                #pragma unroll
                for (int mt = 0; mt < 2; mt++) {
                    asm volatile(
                        "mma.sync.aligned.m16n8k8.row.col.f32.tf32.tf32.f32 "
                        "{%0,%1,%2,%3}, {%4,%5,%6,%7}, {%8,%9}, {%0,%1,%2,%3};\n"
                        : "+f"(acc[mt][nt][0]), "+f"(acc[mt][nt][1]),
                          "+f"(acc[mt][nt][2]), "+f"(acc[mt][nt][3])
                        : "r"(a[mt][0]), "r"(a[mt][1]), "r"(a[mt][2]), "r"(a[mt][3]),
                          "r"(b0), "r"(b1));
                }
            }
        }
        __syncthreads();
    }

    const int c2 = c * 2;
    #pragma unroll
    for (int nt = 0; nt < 8; nt++) {
        int col = wn + nt * 8 + c2;
        float bi0 = bias[col], bi1 = bias[col + 1];
        #pragma unroll
        for (int mt = 0; mt < 2; mt++) {
            int r = row0 + wm + mt * 16 + g;
            if (r < M) {
                float rs = rowscale ? rowscale[r] : 1.0f;
                float ox = fmaxf(acc[mt][nt][0] + bi0, 0.f) * rs;
                float oy = fmaxf(acc[mt][nt][1] + bi1, 0.f) * rs;
                if (HALF_OUT)
                    ((__half2*)outp)[r * 64 + (col >> 1)] = __floats2half2_rn(ox, oy);
                else
                    ((float2*)outp)[r * 64 + (col >> 1)] = make_float2(ox, oy);
            }
            int r2 = r + 8;
            if (r2 < M) {
                float rs = rowscale ? rowscale[r2] : 1.0f;
                float ox = fmaxf(acc[mt][nt][2] + bi0, 0.f) * rs;
                float oy = fmaxf(acc[mt][nt][3] + bi1, 0.f) * rs;
                if (HALF_OUT)
                    ((__half2*)outp)[r2 * 64 + (col >> 1)] = __floats2half2_rn(ox, oy);
                else
                    ((float2*)outp)[r2 * 64 + (col >> 1)] = make_float2(ox, oy);
            }
        }
    }
}

// ---------------- launch (single stream) ----------------
extern "C" void kernel_launch(void* const* d_in, const int* in_sizes, int n_in,
                              void* d_out, int out_size)
{
    const int*   batch = (const int*)d_in[0];
    const int*   src   = (const int*)d_in[1];
    const int*   dst   = (const int*)d_in[2];
    const float* emb   = (const float*)d_in[3];
    const float* W1    = (const float*)d_in[4];
    const float* b1    = (const float*)d_in[5];
    const float* W2    = (const float*)d_in[6];
    const float* b2    = (const float*)d_in[7];
    const float* W3    = (const float*)d_in[8];
    const float* b3    = (const float*)d_in[9];

    __half2* hbuf;  cudaGetSymbolAddress((void**)&hbuf, g_hh);
    float4* aggbuf; cudaGetSymbolAddress((void**)&aggbuf, g_agg);
    int* degp;      cudaGetSymbolAddress((void**)&degp, g_deg);
    float* nsrc;    cudaGetSymbolAddress((void**)&nsrc, g_norm_src);

    cudaFuncSetAttribute(k_gemm_tf32<true>,
                         cudaFuncAttributeMaxDynamicSharedMemorySize, GEMM_SMEM);
    cudaFuncSetAttribute(k_gemm_tf32<false>,
                         cudaFuncAttributeMaxDynamicSharedMemorySize, GEMM_SMEM);

    const int scan_blocks = (NN + 1023) / 1024;   // 49

    cudaMemsetAsync(degp, 0, 2 * NN * sizeof(int), 0);
    k_degree<<<(EE / 4 + 255) / 256, 256>>>((const int4*)src, (const int4*)dst);
    k_scan1n<<<scan_blocks, 1024>>>();
    k_h0<<<(NN * 32 + 255) / 256, 256>>>(batch, (const float4*)emb);
    k_scan3<<<(NN + 255) / 256, 256>>>();
    k_fill<<<(EE / 4 + 255) / 256, 256>>>((const int4*)src, (const int4*)dst);

    const int gemm_grid = (NN + 127) / 128;       // 391
    const int spmm_grid = (NN + 7) / 8;

    // layer 1
    k_spmm<<<spmm_grid, 256>>>();
    k_gemm_tf32<true><<<gemm_grid, 256, GEMM_SMEM>>>(aggbuf, (const float4*)W1, b1,
                                                     nsrc, hbuf, NN);
    // layer 2
    k_spmm<<<spmm_grid, 256>>>();
    k_gemm_tf32<true><<<gemm_grid, 256, GEMM_SMEM>>>(aggbuf, (const float4*)W2, b2,
                                                     nsrc, hbuf, NN);
    // layer 3 -> d_out (fp32, no rowscale)
    k_spmm<<<spmm_grid, 256>>>();
    k_gemm_tf32<false><<<gemm_grid, 256, GEMM_SMEM>>>(aggbuf, (const float4*)W3, b3,
                                                      nullptr, d_out, NN);
}

// round 10
// speedup vs baseline: 1.7102x; 1.0325x over previous
#include <cuda_runtime.h>
#include <cuda_fp16.h>

#define NN 50000
#define EE 800000
#define DD 128

// ---------------- device scratch (no allocs allowed) ----------------
__device__ __half2 g_hh[NN * 64];    // current layer input, fp16, pre-scaled by norm_src
__device__ __half2 g_agg[NN * 64];   // SpMM output, fp16 (already * norm_dst)
__device__ int     g_deg[2 * NN];    // [0,NN)=deg_out, [NN,2NN)=deg_in
__device__ float   g_norm_src[NN];
__device__ float   g_norm_dst[NN];
__device__ int     g_row_ptr[NN + 1];
__device__ int     g_cursor[NN];
__device__ int     g_col[EE];        // src ids grouped by dst
__device__ int     g_bsum[64];

// ---------------- setup kernels ----------------
__global__ void k_degree(const int4* __restrict__ src4, const int4* __restrict__ dst4) {
    int t = blockIdx.x * blockDim.x + threadIdx.x;
    if (t < EE / 4) {
        int4 s = src4[t];
        int4 d = dst4[t];
        atomicAdd(&g_deg[s.x], 1); atomicAdd(&g_deg[s.y], 1);
        atomicAdd(&g_deg[s.z], 1); atomicAdd(&g_deg[s.w], 1);
        atomicAdd(&g_deg[NN + d.x], 1); atomicAdd(&g_deg[NN + d.y], 1);
        atomicAdd(&g_deg[NN + d.z], 1); atomicAdd(&g_deg[NN + d.w], 1);
    }
}

// scan phase 1 over deg_in (1024/block) + norms (fused)
__global__ void k_scan1n() {
    __shared__ int warp_sums[32];
    const int tid = threadIdx.x;
    int i = blockIdx.x * 1024 + tid;
    int v = 0;
    if (i < NN) {
        int dout = g_deg[i];      if (dout < 1) dout = 1;
        int din  = g_deg[NN + i];
        v = din;
        if (din < 1) din = 1;
        g_norm_src[i] = rsqrtf((float)dout);
        g_norm_dst[i] = rsqrtf((float)din);
    }
    int x = v;
    #pragma unroll
    for (int off = 1; off < 32; off <<= 1) {
        int y = __shfl_up_sync(0xffffffffu, x, off);
        if ((tid & 31) >= off) x += y;
    }
    if ((tid & 31) == 31) warp_sums[tid >> 5] = x;
    __syncthreads();
    if (tid < 32) {
        int w = warp_sums[tid];
        #pragma unroll
        for (int off = 1; off < 32; off <<= 1) {
            int y = __shfl_up_sync(0xffffffffu, w, off);
            if (tid >= off) w += y;
        }
        warp_sums[tid] = w;
    }
    __syncthreads();
    int warp_off = (tid >= 32) ? warp_sums[(tid >> 5) - 1] : 0;
    int incl = x + warp_off;
    if (i < NN) g_row_ptr[i] = incl - v;       // local exclusive
    if (tid == 1023) g_bsum[blockIdx.x] = incl;
}

// scan phase 2 (merged): each block derives its 1024-group offset from g_bsum
__global__ void k_scan3() {
    __shared__ int s_off;
    const int tid = threadIdx.x;
    const int grp = blockIdx.x >> 2;
    if (tid < 32) {
        int a = (tid < grp)      ? g_bsum[tid]      : 0;
        int b = (tid + 32 < grp) ? g_bsum[tid + 32] : 0;
        int s = a + b;
        #pragma unroll
        for (int off = 16; off > 0; off >>= 1)
            s += __shfl_down_sync(0xffffffffu, s, off);
        if (tid == 0) s_off = s;
    }
    __syncthreads();
    int i = blockIdx.x * 256 + tid;
    if (i < NN) {
        int val = g_row_ptr[i] + s_off;
        g_row_ptr[i] = val;
        g_cursor[i]  = val;
    }
    if (i == 0) g_row_ptr[NN] = EE;
}

__global__ void k_fill(const int4* __restrict__ src4, const int4* __restrict__ dst4) {
    int t = blockIdx.x * blockDim.x + threadIdx.x;
    if (t < EE / 4) {
        int4 s = src4[t];
        int4 d = dst4[t];
        g_col[atomicAdd(&g_cursor[d.x], 1)] = s.x;
        g_col[atomicAdd(&g_cursor[d.y], 1)] = s.y;
        g_col[atomicAdd(&g_cursor[d.z], 1)] = s.z;
        g_col[atomicAdd(&g_cursor[d.w], 1)] = s.w;
    }
}

// h0 = half(emb[batch] * norm_src)   (requires norms; runs after k_scan1n)
__global__ void k_h0(const int* __restrict__ batch, const float4* __restrict__ emb) {
    int idx = blockIdx.x * blockDim.x + threadIdx.x;
    if (idx >= NN * 32) return;
    int i = idx >> 5, q = idx & 31;
    float ns = g_norm_src[i];
    float4 v = emb[(size_t)batch[i] * 32 + q];
    __half2 p0 = __floats2half2_rn(v.x * ns, v.y * ns);
    __half2 p1 = __floats2half2_rn(v.z * ns, v.w * ns);
    uint2 o = make_uint2(*(unsigned*)&p0, *(unsigned*)&p1);
    ((uint2*)g_hh)[idx] = o;
}

// ---------------- SpMM: pull-style, warp per dst node, fp16 gather / fp32 acc ----------------
__global__ void k_spmm() {
    int warp = (blockIdx.x * blockDim.x + threadIdx.x) >> 5;
    int lane = threadIdx.x & 31;
    if (warp >= NN) return;
    const uint2* hp = (const uint2*)g_hh;      // row stride = 32 uint2 (128 halves)
    int beg = g_row_ptr[warp];
    int end = g_row_ptr[warp + 1];
    float4 acc = make_float4(0.f, 0.f, 0.f, 0.f);
    for (int j0 = beg; j0 < end; j0 += 32) {
        int c = 0;
        if (j0 + lane < end) c = g_col[j0 + lane];
        int n = end - j0; if (n > 32) n = 32;
        int t = 0;
        for (; t + 3 < n; t += 4) {
            int s0 = __shfl_sync(0xffffffffu, c, t);
            int s1 = __shfl_sync(0xffffffffu, c, t + 1);
            int s2 = __shfl_sync(0xffffffffu, c, t + 2);
            int s3 = __shfl_sync(0xffffffffu, c, t + 3);
            uint2 u0 = hp[s0 * 32 + lane];
            uint2 u1 = hp[s1 * 32 + lane];
            uint2 u2 = hp[s2 * 32 + lane];
            uint2 u3 = hp[s3 * 32 + lane];
            float2 a0 = __half22float2(*(__half2*)&u0.x);
            float2 b0 = __half22float2(*(__half2*)&u0.y);
            float2 a1 = __half22float2(*(__half2*)&u1.x);
            float2 b1 = __half22float2(*(__half2*)&u1.y);
            float2 a2 = __half22float2(*(__half2*)&u2.x);
            float2 b2 = __half22float2(*(__half2*)&u2.y);
            float2 a3 = __half22float2(*(__half2*)&u3.x);
            float2 b3 = __half22float2(*(__half2*)&u3.y);
            acc.x += a0.x + a1.x + a2.x + a3.x;
            acc.y += a0.y + a1.y + a2.y + a3.y;
            acc.z += b0.x + b1.x + b2.x + b3.x;
            acc.w += b0.y + b1.y + b2.y + b3.y;
        }
        for (; t < n; t++) {
            int s = __shfl_sync(0xffffffffu, c, t);
            uint2 u = hp[s * 32 + lane];
            float2 a = __half22float2(*(__half2*)&u.x);
            float2 b = __half22float2(*(__half2*)&u.y);
            acc.x += a.x; acc.y += a.y; acc.z += b.x; acc.w += b.y;
        }
    }
    float nd = g_norm_dst[warp];
    __half2 p0 = __floats2half2_rn(acc.x * nd, acc.y * nd);
    __half2 p1 = __floats2half2_rn(acc.z * nd, acc.w * nd);
    uint2 o = make_uint2(*(unsigned*)&p0, *(unsigned*)&p1);
    ((uint2*)g_agg)[warp * 32 + lane] = o;
}

// ---------------- TF32 tensor-core GEMM: out = relu(A @ W + b) [* rowscale] ----------------
// A is fp16 (half2-packed), M x 128, row stride 32 uint2.
__device__ __forceinline__ unsigned f2tf(float f) {
    unsigned u;
    asm("cvt.rna.tf32.f32 %0, %1;" : "=r"(u) : "f"(f));
    return u;
}

#define AS_STRIDE 68
#define BS_STRIDE 136
#define GEMM_SMEM ((128 * AS_STRIDE + 64 * BS_STRIDE) * 4)

template <bool HALF_OUT>
__global__ __launch_bounds__(256, 2) void k_gemm_tf32(
    const uint2* __restrict__ A2, const float4* __restrict__ W4,
    const float* __restrict__ bias, const float* __restrict__ rowscale,
    void* __restrict__ outp, int M)
{
    extern __shared__ unsigned smem[];
    unsigned* As = smem;                       // [128][68]
    unsigned* Bs = smem + 128 * AS_STRIDE;     // [64][136]

    const int tid  = threadIdx.x;
    const int wid  = tid >> 5;
    const int lane = tid & 31;
    const int g = lane >> 2;       // 0..7
    const int c = lane & 3;        // 0..3
    const int wm = (wid & 3) * 32;
    const int wn = (wid >> 2) * 64;
    const int row0 = blockIdx.x * 128;

    float acc[2][8][4];
    #pragma unroll
    for (int i = 0; i < 2; i++)
        #pragma unroll
        for (int j = 0; j < 8; j++)
            #pragma unroll
            for (int k = 0; k < 4; k++) acc[i][j][k] = 0.f;

    for (int k0 = 0; k0 < 128; k0 += 64) {
        #pragma unroll
        for (int l = 0; l < 8; l++) {
            int idx = l * 256 + tid;
            int r = idx >> 4;
            int q = idx & 15;
            float4 v = make_float4(0.f, 0.f, 0.f, 0.f);
            if (row0 + r < M) {
                uint2 u = A2[(row0 + r) * 32 + (k0 >> 2) + q];
                float2 a = __half22float2(*(__half2*)&u.x);
                float2 b = __half22float2(*(__half2*)&u.y);
                v = make_float4(a.x, a.y, b.x, b.y);
            }
            uint4 t = make_uint4(f2tf(v.x), f2tf(v.y), f2tf(v.z), f2tf(v.w));
            *(uint4*)&As[r * AS_STRIDE + q * 4] = t;
        }
        #pragma unroll
        for (int l = 0; l < 8; l++) {
            int idx = l * 256 + tid;
            int k = idx >> 5;
            int nq = idx & 31;
            float4 v = __ldg(&W4[(size_t)(k0 + k) * 32 + nq]);
            uint4 t = make_uint4(f2tf(v.x), f2tf(v.y), f2tf(v.z), f2tf(v.w));
            *(uint4*)&Bs[k * BS_STRIDE + nq * 4] = t;
        }
        __syncthreads();

        #pragma unroll
        for (int kk = 0; kk < 64; kk += 8) {
            unsigned a[2][4];
            #pragma unroll
            for (int mt = 0; mt < 2; mt++) {
                int r = wm + mt * 16 + g;
                a[mt][0] = As[r * AS_STRIDE + kk + c];
                a[mt][1] = As[(r + 8) * AS_STRIDE + kk + c];
                a[mt][2] = As[r * AS_STRIDE + kk + c + 4];
                a[mt][3] = As[(r + 8) * AS_STRIDE + kk + c + 4];
            }
            #pragma unroll
            for (int nt = 0; nt < 8; nt++) {
                unsigned b0 = Bs[(kk + c) * BS_STRIDE + wn + nt * 8 + g];
                unsigned b1 = Bs[(kk + c + 4) * BS_STRIDE + wn + nt * 8 + g];
                #pragma unroll
                for (int mt = 0; mt < 2; mt++) {
                    asm volatile(
                        "mma.sync.aligned.m16n8k8.row.col.f32.tf32.tf32.f32 "
                        "{%0,%1,%2,%3}, {%4,%5,%6,%7}, {%8,%9}, {%0,%1,%2,%3};\n"
                        : "+f"(acc[mt][nt][0]), "+f"(acc[mt][nt][1]),
                          "+f"(acc[mt][nt][2]), "+f"(acc[mt][nt][3])
                        : "r"(a[mt][0]), "r"(a[mt][1]), "r"(a[mt][2]), "r"(a[mt][3]),
                          "r"(b0), "r"(b1));
                }
            }
        }
        __syncthreads();
    }

    const int c2 = c * 2;
    #pragma unroll
    for (int nt = 0; nt < 8; nt++) {
        int col = wn + nt * 8 + c2;
        float bi0 = bias[col], bi1 = bias[col + 1];
        #pragma unroll
        for (int mt = 0; mt < 2; mt++) {
            int r = row0 + wm + mt * 16 + g;
            if (r < M) {
                float rs = rowscale ? rowscale[r] : 1.0f;
                float ox = fmaxf(acc[mt][nt][0] + bi0, 0.f) * rs;
                float oy = fmaxf(acc[mt][nt][1] + bi1, 0.f) * rs;
                if (HALF_OUT)
                    ((__half2*)outp)[r * 64 + (col >> 1)] = __floats2half2_rn(ox, oy);
                else
                    ((float2*)outp)[r * 64 + (col >> 1)] = make_float2(ox, oy);
            }
            int r2 = r + 8;
            if (r2 < M) {
                float rs = rowscale ? rowscale[r2] : 1.0f;
                float ox = fmaxf(acc[mt][nt][2] + bi0, 0.f) * rs;
                float oy = fmaxf(acc[mt][nt][3] + bi1, 0.f) * rs;
                if (HALF_OUT)
                    ((__half2*)outp)[r2 * 64 + (col >> 1)] = __floats2half2_rn(ox, oy);
                else
                    ((float2*)outp)[r2 * 64 + (col >> 1)] = make_float2(ox, oy);
            }
        }
    }
}

// ---------------- launch (single stream) ----------------
extern "C" void kernel_launch(void* const* d_in, const int* in_sizes, int n_in,
                              void* d_out, int out_size)
{
    const int*   batch = (const int*)d_in[0];
    const int*   src   = (const int*)d_in[1];
    const int*   dst   = (const int*)d_in[2];
    const float* emb   = (const float*)d_in[3];
    const float* W1    = (const float*)d_in[4];
    const float* b1    = (const float*)d_in[5];
    const float* W2    = (const float*)d_in[6];
    const float* b2    = (const float*)d_in[7];
    const float* W3    = (const float*)d_in[8];
    const float* b3    = (const float*)d_in[9];

    __half2* hbuf;  cudaGetSymbolAddress((void**)&hbuf, g_hh);
    __half2* aggbuf; cudaGetSymbolAddress((void**)&aggbuf, g_agg);
    int* degp;      cudaGetSymbolAddress((void**)&degp, g_deg);
    float* nsrc;    cudaGetSymbolAddress((void**)&nsrc, g_norm_src);

    cudaFuncSetAttribute(k_gemm_tf32<true>,
                         cudaFuncAttributeMaxDynamicSharedMemorySize, GEMM_SMEM);
    cudaFuncSetAttribute(k_gemm_tf32<false>,
                         cudaFuncAttributeMaxDynamicSharedMemorySize, GEMM_SMEM);

    const int scan_blocks = (NN + 1023) / 1024;   // 49

    cudaMemsetAsync(degp, 0, 2 * NN * sizeof(int), 0);
    k_degree<<<(EE / 4 + 255) / 256, 256>>>((const int4*)src, (const int4*)dst);
    k_scan1n<<<scan_blocks, 1024>>>();
    k_h0<<<(NN * 32 + 255) / 256, 256>>>(batch, (const float4*)emb);
    k_scan3<<<(NN + 255) / 256, 256>>>();
    k_fill<<<(EE / 4 + 255) / 256, 256>>>((const int4*)src, (const int4*)dst);

    const int gemm_grid = (NN + 127) / 128;       // 391
    const int spmm_grid = (NN + 7) / 8;

    // layer 1
    k_spmm<<<spmm_grid, 256>>>();
    k_gemm_tf32<true><<<gemm_grid, 256, GEMM_SMEM>>>((const uint2*)aggbuf,
                                                     (const float4*)W1, b1,
                                                     nsrc, hbuf, NN);
    // layer 2
    k_spmm<<<spmm_grid, 256>>>();
    k_gemm_tf32<true><<<gemm_grid, 256, GEMM_SMEM>>>((const uint2*)aggbuf,
                                                     (const float4*)W2, b2,
                                                     nsrc, hbuf, NN);
    // layer 3 -> d_out (fp32, no rowscale)
    k_spmm<<<spmm_grid, 256>>>();
    k_gemm_tf32<false><<<gemm_grid, 256, GEMM_SMEM>>>((const uint2*)aggbuf,
                                                      (const float4*)W3, b3,
                                                      nullptr, d_out, NN);
}

// round 11
// speedup vs baseline: 2.0087x; 1.1746x over previous
#include <cuda_runtime.h>
#include <cuda_fp16.h>

#define NN 50000
#define EE 800000
#define DD 128

// ---------------- device scratch (no allocs allowed) ----------------
__device__ __half2  g_hh[NN * 64];   // current layer input, fp16, pre-scaled by norm_src
__device__ __half2  g_agg[NN * 64];  // SpMM output, fp16 (already * norm_dst)
__device__ unsigned g_wt[3 * 8192];  // W1..W3 as fp16, n-major: wt[l][n][k] (half2 over k)
__device__ int      g_deg[2 * NN];   // [0,NN)=deg_out, [NN,2NN)=deg_in
__device__ float    g_norm_src[NN];
__device__ float    g_norm_dst[NN];
__device__ int      g_row_ptr[NN + 1];
__device__ int      g_cursor[NN];
__device__ int      g_col[EE];       // src ids grouped by dst
__device__ int      g_bsum[64];

// ---------------- setup kernels ----------------
__global__ void k_degree(const int4* __restrict__ src4, const int4* __restrict__ dst4) {
    int t = blockIdx.x * blockDim.x + threadIdx.x;
    if (t < EE / 4) {
        int4 s = src4[t];
        int4 d = dst4[t];
        atomicAdd(&g_deg[s.x], 1); atomicAdd(&g_deg[s.y], 1);
        atomicAdd(&g_deg[s.z], 1); atomicAdd(&g_deg[s.w], 1);
        atomicAdd(&g_deg[NN + d.x], 1); atomicAdd(&g_deg[NN + d.y], 1);
        atomicAdd(&g_deg[NN + d.z], 1); atomicAdd(&g_deg[NN + d.w], 1);
    }
}

// W[k][n] fp32 -> wt[l][n][k] fp16 (half2 packed over k). Runs once, independent.
__global__ void k_wconv(const float* __restrict__ W1, const float* __restrict__ W2,
                        const float* __restrict__ W3) {
    int idx = blockIdx.x * blockDim.x + threadIdx.x;   // 0 .. 3*8192-1
    if (idx >= 3 * 128 * 64) return;
    int l   = idx >> 13;
    int rem = idx & 8191;
    int kp  = rem >> 7;        // 0..63 (pair of k)
    int n   = rem & 127;
    const float* W = (l == 0) ? W1 : (l == 1) ? W2 : W3;
    __half2 h = __floats2half2_rn(W[(2 * kp) * 128 + n], W[(2 * kp + 1) * 128 + n]);
    g_wt[l * 8192 + n * 64 + kp] = *(unsigned*)&h;
}

// scan phase 1 over deg_in (1024/block) + norms (fused)
__global__ void k_scan1n() {
    __shared__ int warp_sums[32];
    const int tid = threadIdx.x;
    int i = blockIdx.x * 1024 + tid;
    int v = 0;
    if (i < NN) {
        int dout = g_deg[i];      if (dout < 1) dout = 1;
        int din  = g_deg[NN + i];
        v = din;
        if (din < 1) din = 1;
        g_norm_src[i] = rsqrtf((float)dout);
        g_norm_dst[i] = rsqrtf((float)din);
    }
    int x = v;
    #pragma unroll
    for (int off = 1; off < 32; off <<= 1) {
        int y = __shfl_up_sync(0xffffffffu, x, off);
        if ((tid & 31) >= off) x += y;
    }
    if ((tid & 31) == 31) warp_sums[tid >> 5] = x;
    __syncthreads();
    if (tid < 32) {
        int w = warp_sums[tid];
        #pragma unroll
        for (int off = 1; off < 32; off <<= 1) {
            int y = __shfl_up_sync(0xffffffffu, w, off);
            if (tid >= off) w += y;
        }
        warp_sums[tid] = w;
    }
    __syncthreads();
    int warp_off = (tid >= 32) ? warp_sums[(tid >> 5) - 1] : 0;
    int incl = x + warp_off;
    if (i < NN) g_row_ptr[i] = incl - v;       // local exclusive
    if (tid == 1023) g_bsum[blockIdx.x] = incl;
}

// scan phase 2 (merged): each block derives its 1024-group offset from g_bsum
__global__ void k_scan3() {
    __shared__ int s_off;
    const int tid = threadIdx.x;
    const int grp = blockIdx.x >> 2;
    if (tid < 32) {
        int a = (tid < grp)      ? g_bsum[tid]      : 0;
        int b = (tid + 32 < grp) ? g_bsum[tid + 32] : 0;
        int s = a + b;
        #pragma unroll
        for (int off = 16; off > 0; off >>= 1)
            s += __shfl_down_sync(0xffffffffu, s, off);
        if (tid == 0) s_off = s;
    }
    __syncthreads();
    int i = blockIdx.x * 256 + tid;
    if (i < NN) {
        int val = g_row_ptr[i] + s_off;
        g_row_ptr[i] = val;
        g_cursor[i]  = val;
    }
    if (i == 0) g_row_ptr[NN] = EE;
}

__global__ void k_fill(const int4* __restrict__ src4, const int4* __restrict__ dst4) {
    int t = blockIdx.x * blockDim.x + threadIdx.x;
    if (t < EE / 4) {
        int4 s = src4[t];
        int4 d = dst4[t];
        g_col[atomicAdd(&g_cursor[d.x], 1)] = s.x;
        g_col[atomicAdd(&g_cursor[d.y], 1)] = s.y;
        g_col[atomicAdd(&g_cursor[d.z], 1)] = s.z;
        g_col[atomicAdd(&g_cursor[d.w], 1)] = s.w;
    }
}

// h0 = half(emb[batch] * norm_src)   (requires norms; runs after k_scan1n)
__global__ void k_h0(const int* __restrict__ batch, const float4* __restrict__ emb) {
    int idx = blockIdx.x * blockDim.x + threadIdx.x;
    if (idx >= NN * 32) return;
    int i = idx >> 5, q = idx & 31;
    float ns = g_norm_src[i];
    float4 v = emb[(size_t)batch[i] * 32 + q];
    __half2 p0 = __floats2half2_rn(v.x * ns, v.y * ns);
    __half2 p1 = __floats2half2_rn(v.z * ns, v.w * ns);
    uint2 o = make_uint2(*(unsigned*)&p0, *(unsigned*)&p1);
    ((uint2*)g_hh)[idx] = o;
}

// ---------------- SpMM: pull-style, warp per dst node, fp16 gather / fp32 acc ----------------
__global__ void k_spmm() {
    int warp = (blockIdx.x * blockDim.x + threadIdx.x) >> 5;
    int lane = threadIdx.x & 31;
    if (warp >= NN) return;
    const uint2* hp = (const uint2*)g_hh;      // row stride = 32 uint2 (128 halves)
    int beg = g_row_ptr[warp];
    int end = g_row_ptr[warp + 1];
    float4 acc = make_float4(0.f, 0.f, 0.f, 0.f);
    for (int j0 = beg; j0 < end; j0 += 32) {
        int c = 0;
        if (j0 + lane < end) c = g_col[j0 + lane];
        int n = end - j0; if (n > 32) n = 32;
        int t = 0;
        for (; t + 3 < n; t += 4) {
            int s0 = __shfl_sync(0xffffffffu, c, t);
            int s1 = __shfl_sync(0xffffffffu, c, t + 1);
            int s2 = __shfl_sync(0xffffffffu, c, t + 2);
            int s3 = __shfl_sync(0xffffffffu, c, t + 3);
            uint2 u0 = hp[s0 * 32 + lane];
            uint2 u1 = hp[s1 * 32 + lane];
            uint2 u2 = hp[s2 * 32 + lane];
            uint2 u3 = hp[s3 * 32 + lane];
            float2 a0 = __half22float2(*(__half2*)&u0.x);
            float2 b0 = __half22float2(*(__half2*)&u0.y);
            float2 a1 = __half22float2(*(__half2*)&u1.x);
            float2 b1 = __half22float2(*(__half2*)&u1.y);
            float2 a2 = __half22float2(*(__half2*)&u2.x);
            float2 b2 = __half22float2(*(__half2*)&u2.y);
            float2 a3 = __half22float2(*(__half2*)&u3.x);
            float2 b3 = __half22float2(*(__half2*)&u3.y);
            acc.x += a0.x + a1.x + a2.x + a3.x;
            acc.y += a0.y + a1.y + a2.y + a3.y;
            acc.z += b0.x + b1.x + b2.x + b3.x;
            acc.w += b0.y + b1.y + b2.y + b3.y;
        }
        for (; t < n; t++) {
            int s = __shfl_sync(0xffffffffu, c, t);
            uint2 u = hp[s * 32 + lane];
            float2 a = __half22float2(*(__half2*)&u.x);
            float2 b = __half22float2(*(__half2*)&u.y);
            acc.x += a.x; acc.y += a.y; acc.z += b.x; acc.w += b.y;
        }
    }
    float nd = g_norm_dst[warp];
    __half2 p0 = __floats2half2_rn(acc.x * nd, acc.y * nd);
    __half2 p1 = __floats2half2_rn(acc.z * nd, acc.w * nd);
    uint2 o = make_uint2(*(unsigned*)&p0, *(unsigned*)&p1);
    ((uint2*)g_agg)[warp * 32 + lane] = o;
}

// ---------------- FP16 tensor-core GEMM: out = relu(A @ W + b) [* rowscale] ----------------
// A: fp16 [M][128] (uint2-packed, row stride 32). B: g_wt n-major fp16 [128][128].
// mma.m16n8k16.row.col.f32.f16.f16.f32; single-shot smem (no K loop).
#define ASH 68   // half2 per A smem row
#define BSH 66   // half2 per B smem row
#define GEMM_SMEM ((128 * ASH + 128 * BSH) * 4)   // 68608 B

template <bool HALF_OUT>
__global__ __launch_bounds__(256, 2) void k_gemm_f16(
    const uint2* __restrict__ A2, const uint2* __restrict__ WT2,
    const float* __restrict__ bias, const float* __restrict__ rowscale,
    void* __restrict__ outp, int M)
{
    extern __shared__ unsigned smem[];
    unsigned* As = smem;                  // [128][ASH] half2
    unsigned* Bs = smem + 128 * ASH;      // [128][BSH] half2, n-major

    const int tid  = threadIdx.x;
    const int wid  = tid >> 5;
    const int lane = tid & 31;
    const int g = lane >> 2;       // 0..7
    const int c = lane & 3;        // 0..3
    const int wm = (wid & 3) * 32;
    const int wn = (wid >> 2) * 64;
    const int row0 = blockIdx.x * 128;

    // load A tile (pure copy, fp16 already)
    #pragma unroll
    for (int l = 0; l < 16; l++) {
        int idx = l * 256 + tid;       // 0..4095
        int r = idx >> 5;              // 0..127
        int q = idx & 31;              // uint2 within row
        uint2 u = make_uint2(0u, 0u);
        if (row0 + r < M) u = A2[(row0 + r) * 32 + q];
        *(uint2*)&As[r * ASH + q * 2] = u;
    }
    // load B tile (pure copy from n-major fp16 W)
    #pragma unroll
    for (int l = 0; l < 16; l++) {
        int idx = l * 256 + tid;
        int n = idx >> 5;
        int q = idx & 31;
        uint2 u = WT2[n * 32 + q];
        *(uint2*)&Bs[n * BSH + q * 2] = u;
    }
    __syncthreads();

    float acc[2][8][4];
    #pragma unroll
    for (int i = 0; i < 2; i++)
        #pragma unroll
        for (int j = 0; j < 8; j++)
            #pragma unroll
            for (int k = 0; k < 4; k++) acc[i][j][k] = 0.f;

    #pragma unroll
    for (int s = 0; s < 8; s++) {          // 8 x k16 steps
        const int ko = s * 8;
        unsigned a[2][4];
        #pragma unroll
        for (int mt = 0; mt < 2; mt++) {
            int r = wm + mt * 16 + g;
            a[mt][0] = As[r * ASH + ko + c];
            a[mt][1] = As[(r + 8) * ASH + ko + c];
            a[mt][2] = As[r * ASH + ko + c + 4];
            a[mt][3] = As[(r + 8) * ASH + ko + c + 4];
        }
        #pragma unroll
        for (int nt = 0; nt < 8; nt++) {
            int col = wn + nt * 8 + g;
            unsigned b0 = Bs[col * BSH + ko + c];
            unsigned b1 = Bs[col * BSH + ko + c + 4];
            #pragma unroll
            for (int mt = 0; mt < 2; mt++) {
                asm volatile(
                    "mma.sync.aligned.m16n8k16.row.col.f32.f16.f16.f32 "
                    "{%0,%1,%2,%3}, {%4,%5,%6,%7}, {%8,%9}, {%0,%1,%2,%3};\n"
                    : "+f"(acc[mt][nt][0]), "+f"(acc[mt][nt][1]),
                      "+f"(acc[mt][nt][2]), "+f"(acc[mt][nt][3])
                    : "r"(a[mt][0]), "r"(a[mt][1]), "r"(a[mt][2]), "r"(a[mt][3]),
                      "r"(b0), "r"(b1));
            }
        }
    }

    const int c2 = c * 2;
    #pragma unroll
    for (int nt = 0; nt < 8; nt++) {
        int col = wn + nt * 8 + c2;
        float bi0 = bias[col], bi1 = bias[col + 1];
        #pragma unroll
        for (int mt = 0; mt < 2; mt++) {
            int r = row0 + wm + mt * 16 + g;
            if (r < M) {
                float rs = rowscale ? rowscale[r] : 1.0f;
                float ox = fmaxf(acc[mt][nt][0] + bi0, 0.f) * rs;
                float oy = fmaxf(acc[mt][nt][1] + bi1, 0.f) * rs;
                if (HALF_OUT)
                    ((__half2*)outp)[r * 64 + (col >> 1)] = __floats2half2_rn(ox, oy);
                else
                    ((float2*)outp)[r * 64 + (col >> 1)] = make_float2(ox, oy);
            }
            int r2 = r + 8;
            if (r2 < M) {
                float rs = rowscale ? rowscale[r2] : 1.0f;
                float ox = fmaxf(acc[mt][nt][2] + bi0, 0.f) * rs;
                float oy = fmaxf(acc[mt][nt][3] + bi1, 0.f) * rs;
                if (HALF_OUT)
                    ((__half2*)outp)[r2 * 64 + (col >> 1)] = __floats2half2_rn(ox, oy);
                else
                    ((float2*)outp)[r2 * 64 + (col >> 1)] = make_float2(ox, oy);
            }
        }
    }
}

// ---------------- launch (single stream) ----------------
extern "C" void kernel_launch(void* const* d_in, const int* in_sizes, int n_in,
                              void* d_out, int out_size)
{
    const int*   batch = (const int*)d_in[0];
    const int*   src   = (const int*)d_in[1];
    const int*   dst   = (const int*)d_in[2];
    const float* emb   = (const float*)d_in[3];
    const float* W1    = (const float*)d_in[4];
    const float* b1    = (const float*)d_in[5];
    const float* W2    = (const float*)d_in[6];
    const float* b2    = (const float*)d_in[7];
    const float* W3    = (const float*)d_in[8];
    const float* b3    = (const float*)d_in[9];

    __half2* hbuf;   cudaGetSymbolAddress((void**)&hbuf, g_hh);
    __half2* aggbuf; cudaGetSymbolAddress((void**)&aggbuf, g_agg);
    unsigned* wt;    cudaGetSymbolAddress((void**)&wt, g_wt);
    int* degp;       cudaGetSymbolAddress((void**)&degp, g_deg);
    float* nsrc;     cudaGetSymbolAddress((void**)&nsrc, g_norm_src);

    cudaFuncSetAttribute(k_gemm_f16<true>,
                         cudaFuncAttributeMaxDynamicSharedMemorySize, GEMM_SMEM);
    cudaFuncSetAttribute(k_gemm_f16<false>,
                         cudaFuncAttributeMaxDynamicSharedMemorySize, GEMM_SMEM);

    const int scan_blocks = (NN + 1023) / 1024;   // 49

    cudaMemsetAsync(degp, 0, 2 * NN * sizeof(int), 0);
    k_wconv<<<(3 * 8192 + 255) / 256, 256>>>(W1, W2, W3);
    k_degree<<<(EE / 4 + 255) / 256, 256>>>((const int4*)src, (const int4*)dst);
    k_scan1n<<<scan_blocks, 1024>>>();
    k_h0<<<(NN * 32 + 255) / 256, 256>>>(batch, (const float4*)emb);
    k_scan3<<<(NN + 255) / 256, 256>>>();
    k_fill<<<(EE / 4 + 255) / 256, 256>>>((const int4*)src, (const int4*)dst);

    const int gemm_grid = (NN + 127) / 128;       // 391
    const int spmm_grid = (NN + 7) / 8;

    // layer 1
    k_spmm<<<spmm_grid, 256>>>();
    k_gemm_f16<true><<<gemm_grid, 256, GEMM_SMEM>>>((const uint2*)aggbuf,
                                                    (const uint2*)wt, b1,
                                                    nsrc, hbuf, NN);
    // layer 2
    k_spmm<<<spmm_grid, 256>>>();
    k_gemm_f16<true><<<gemm_grid, 256, GEMM_SMEM>>>((const uint2*)aggbuf,
                                                    (const uint2*)(wt + 8192), b2,
                                                    nsrc, hbuf, NN);
    // layer 3 -> d_out (fp32, no rowscale)
    k_spmm<<<spmm_grid, 256>>>();
    k_gemm_f16<false><<<gemm_grid, 256, GEMM_SMEM>>>((const uint2*)aggbuf,
                                                     (const uint2*)(wt + 16384), b3,
                                                     nullptr, d_out, NN);
}

// round 12
// speedup vs baseline: 2.0715x; 1.0312x over previous
#include <cuda_runtime.h>
#include <cuda_fp16.h>

#define NN 50000
#define EE 800000
#define DD 128

// ---------------- device scratch (no allocs allowed) ----------------
__device__ __half2  g_hh[NN * 64];   // current layer input, fp16, pre-scaled by norm_src
__device__ __half2  g_agg[NN * 64];  // SpMM output, fp16 (already * norm_dst)
__device__ unsigned g_wt[3 * 8192];  // W1..W3 as fp16, n-major: wt[l][n][k] (half2 over k)
__device__ int      g_deg[2 * NN];   // [0,NN)=deg_out, [NN,2NN)=deg_in
__device__ float    g_norm_src[NN];
__device__ float    g_norm_dst[NN];
__device__ int      g_row_ptr[NN + 1];
__device__ int      g_cursor[NN];
__device__ int      g_col[EE];       // src ids grouped by dst
__device__ int      g_bsum[64];

// ---------------- setup kernels ----------------
__global__ void k_degree(const int4* __restrict__ src4, const int4* __restrict__ dst4) {
    int t = blockIdx.x * blockDim.x + threadIdx.x;
    if (t < EE / 4) {
        int4 s = src4[t];
        int4 d = dst4[t];
        atomicAdd(&g_deg[s.x], 1); atomicAdd(&g_deg[s.y], 1);
        atomicAdd(&g_deg[s.z], 1); atomicAdd(&g_deg[s.w], 1);
        atomicAdd(&g_deg[NN + d.x], 1); atomicAdd(&g_deg[NN + d.y], 1);
        atomicAdd(&g_deg[NN + d.z], 1); atomicAdd(&g_deg[NN + d.w], 1);
    }
}

// W[k][n] fp32 -> wt[l][n][k] fp16 (half2 packed over k). Runs once, independent.
__global__ void k_wconv(const float* __restrict__ W1, const float* __restrict__ W2,
                        const float* __restrict__ W3) {
    int idx = blockIdx.x * blockDim.x + threadIdx.x;   // 0 .. 3*8192-1
    if (idx >= 3 * 128 * 64) return;
    int l   = idx >> 13;
    int rem = idx & 8191;
    int kp  = rem >> 7;        // 0..63 (pair of k)
    int n   = rem & 127;
    const float* W = (l == 0) ? W1 : (l == 1) ? W2 : W3;
    __half2 h = __floats2half2_rn(W[(2 * kp) * 128 + n], W[(2 * kp + 1) * 128 + n]);
    g_wt[l * 8192 + n * 64 + kp] = *(unsigned*)&h;
}

// scan phase 1 over deg_in (1024/block) + norms (fused)
__global__ void k_scan1n() {
    __shared__ int warp_sums[32];
    const int tid = threadIdx.x;
    int i = blockIdx.x * 1024 + tid;
    int v = 0;
    if (i < NN) {
        int dout = g_deg[i];      if (dout < 1) dout = 1;
        int din  = g_deg[NN + i];
        v = din;
        if (din < 1) din = 1;
        g_norm_src[i] = rsqrtf((float)dout);
        g_norm_dst[i] = rsqrtf((float)din);
    }
    int x = v;
    #pragma unroll
    for (int off = 1; off < 32; off <<= 1) {
        int y = __shfl_up_sync(0xffffffffu, x, off);
        if ((tid & 31) >= off) x += y;
    }
    if ((tid & 31) == 31) warp_sums[tid >> 5] = x;
    __syncthreads();
    if (tid < 32) {
        int w = warp_sums[tid];
        #pragma unroll
        for (int off = 1; off < 32; off <<= 1) {
            int y = __shfl_up_sync(0xffffffffu, w, off);
            if (tid >= off) w += y;
        }
        warp_sums[tid] = w;
    }
    __syncthreads();
    int warp_off = (tid >= 32) ? warp_sums[(tid >> 5) - 1] : 0;
    int incl = x + warp_off;
    if (i < NN) g_row_ptr[i] = incl - v;       // local exclusive
    if (tid == 1023) g_bsum[blockIdx.x] = incl;
}

// scan phase 2 (merged): each block derives its 1024-group offset from g_bsum
__global__ void k_scan3() {
    __shared__ int s_off;
    const int tid = threadIdx.x;
    const int grp = blockIdx.x >> 2;
    if (tid < 32) {
        int a = (tid < grp)      ? g_bsum[tid]      : 0;
        int b = (tid + 32 < grp) ? g_bsum[tid + 32] : 0;
        int s = a + b;
        #pragma unroll
        for (int off = 16; off > 0; off >>= 1)
            s += __shfl_down_sync(0xffffffffu, s, off);
        if (tid == 0) s_off = s;
    }
    __syncthreads();
    int i = blockIdx.x * 256 + tid;
    if (i < NN) {
        int val = g_row_ptr[i] + s_off;
        g_row_ptr[i] = val;
        g_cursor[i]  = val;
    }
    if (i == 0) g_row_ptr[NN] = EE;
}

__global__ void k_fill(const int4* __restrict__ src4, const int4* __restrict__ dst4) {
    int t = blockIdx.x * blockDim.x + threadIdx.x;
    if (t < EE / 4) {
        int4 s = src4[t];
        int4 d = dst4[t];
        g_col[atomicAdd(&g_cursor[d.x], 1)] = s.x;
        g_col[atomicAdd(&g_cursor[d.y], 1)] = s.y;
        g_col[atomicAdd(&g_cursor[d.z], 1)] = s.z;
        g_col[atomicAdd(&g_cursor[d.w], 1)] = s.w;
    }
}

// h0 = half(emb[batch] * norm_src); 2 float4 per thread (MLP=2)
__global__ void k_h0(const int* __restrict__ batch, const float4* __restrict__ emb) {
    int idx = blockIdx.x * blockDim.x + threadIdx.x;
    if (idx >= NN * 16) return;
    int i = idx >> 4, q = idx & 15;
    float ns = g_norm_src[i];
    const float4* row = emb + (size_t)batch[i] * 32;
    float4 v0 = row[q * 2];
    float4 v1 = row[q * 2 + 1];
    __half2 p0 = __floats2half2_rn(v0.x * ns, v0.y * ns);
    __half2 p1 = __floats2half2_rn(v0.z * ns, v0.w * ns);
    __half2 p2 = __floats2half2_rn(v1.x * ns, v1.y * ns);
    __half2 p3 = __floats2half2_rn(v1.z * ns, v1.w * ns);
    uint4 o = make_uint4(*(unsigned*)&p0, *(unsigned*)&p1,
                         *(unsigned*)&p2, *(unsigned*)&p3);
    ((uint4*)g_hh)[idx] = o;
}

// ---------------- SpMM: warp per dst row; 16 lanes x uint4, 2 edges in flight ----------------
__global__ void k_spmm() {
    int warp = (blockIdx.x * blockDim.x + threadIdx.x) >> 5;
    int lane = threadIdx.x & 31;
    if (warp >= NN) return;
    const uint4* hp = (const uint4*)g_hh;      // row stride = 16 uint4 (128 halves)
    const int hl  = lane & 15;                 // position within row (8 halves)
    const int sel = lane >> 4;                 // which edge of the pair
    int beg = g_row_ptr[warp];
    int end = g_row_ptr[warp + 1];
    float acc[8];
    #pragma unroll
    for (int k = 0; k < 8; k++) acc[k] = 0.f;

    for (int j0 = beg; j0 < end; j0 += 32) {
        int c = 0;
        if (j0 + lane < end) c = g_col[j0 + lane];
        int n = end - j0; if (n > 32) n = 32;
        int t = 0;
        for (; t + 3 < n; t += 4) {
            int s0 = __shfl_sync(0xffffffffu, c, t + sel);
            int s1 = __shfl_sync(0xffffffffu, c, t + 2 + sel);
            uint4 u0 = hp[s0 * 16 + hl];
            uint4 u1 = hp[s1 * 16 + hl];
            float2 f;
            f = __half22float2(*(__half2*)&u0.x); acc[0] += f.x; acc[1] += f.y;
            f = __half22float2(*(__half2*)&u0.y); acc[2] += f.x; acc[3] += f.y;
            f = __half22float2(*(__half2*)&u0.z); acc[4] += f.x; acc[5] += f.y;
            f = __half22float2(*(__half2*)&u0.w); acc[6] += f.x; acc[7] += f.y;
            f = __half22float2(*(__half2*)&u1.x); acc[0] += f.x; acc[1] += f.y;
            f = __half22float2(*(__half2*)&u1.y); acc[2] += f.x; acc[3] += f.y;
            f = __half22float2(*(__half2*)&u1.z); acc[4] += f.x; acc[5] += f.y;
            f = __half22float2(*(__half2*)&u1.w); acc[6] += f.x; acc[7] += f.y;
        }
        for (; t < n; t += 2) {
            int e = t + sel;
            int s = __shfl_sync(0xffffffffu, c, e < 31 ? e : 31);
            if (e < n) {
                uint4 u = hp[s * 16 + hl];
                float2 f;
                f = __half22float2(*(__half2*)&u.x); acc[0] += f.x; acc[1] += f.y;
                f = __half22float2(*(__half2*)&u.y); acc[2] += f.x; acc[3] += f.y;
                f = __half22float2(*(__half2*)&u.z); acc[4] += f.x; acc[5] += f.y;
                f = __half22float2(*(__half2*)&u.w); acc[6] += f.x; acc[7] += f.y;
            }
        }
    }
    // combine the two edge-halves: lanes L and L+16 hold the same columns
    #pragma unroll
    for (int k = 0; k < 8; k++) acc[k] += __shfl_xor_sync(0xffffffffu, acc[k], 16);

    if (sel == 0) {
        float nd = g_norm_dst[warp];
        __half2 p0 = __floats2half2_rn(acc[0] * nd, acc[1] * nd);
        __half2 p1 = __floats2half2_rn(acc[2] * nd, acc[3] * nd);
        __half2 p2 = __floats2half2_rn(acc[4] * nd, acc[5] * nd);
        __half2 p3 = __floats2half2_rn(acc[6] * nd, acc[7] * nd);
        uint4 o = make_uint4(*(unsigned*)&p0, *(unsigned*)&p1,
                             *(unsigned*)&p2, *(unsigned*)&p3);
        ((uint4*)g_agg)[warp * 16 + hl] = o;
    }
}

// ---------------- FP16 tensor-core GEMM: out = relu(A @ W + b) [* rowscale] ----------------
#define ASH 68   // half2 per A smem row
#define BSH 66   // half2 per B smem row
#define GEMM_SMEM ((128 * ASH + 128 * BSH) * 4)   // 68608 B

template <bool HALF_OUT>
__global__ __launch_bounds__(256, 2) void k_gemm_f16(
    const uint4* __restrict__ A4, const uint2* __restrict__ WT2,
    const float* __restrict__ bias, const float* __restrict__ rowscale,
    void* __restrict__ outp, int M)
{
    extern __shared__ unsigned smem[];
    unsigned* As = smem;                  // [128][ASH] half2
    unsigned* Bs = smem + 128 * ASH;      // [128][BSH] half2, n-major

    const int tid  = threadIdx.x;
    const int wid  = tid >> 5;
    const int lane = tid & 31;
    const int g = lane >> 2;       // 0..7
    const int c = lane & 3;        // 0..3
    const int wm = (wid & 3) * 32;
    const int wn = (wid >> 2) * 64;
    const int row0 = blockIdx.x * 128;

    // load A tile: 128 rows x 16 uint4 (pure copy)
    #pragma unroll
    for (int l = 0; l < 8; l++) {
        int idx = l * 256 + tid;       // 0..2047
        int r = idx >> 4;              // 0..127
        int q = idx & 15;              // uint4 within row
        uint4 u = make_uint4(0u, 0u, 0u, 0u);
        if (row0 + r < M) u = A4[(row0 + r) * 16 + q];
        *(uint4*)&As[r * ASH + q * 4] = u;
    }
    // load B tile (pure copy from n-major fp16 W)
    #pragma unroll
    for (int l = 0; l < 16; l++) {
        int idx = l * 256 + tid;
        int n = idx >> 5;
        int q = idx & 31;
        uint2 u = WT2[n * 32 + q];
        *(uint2*)&Bs[n * BSH + q * 2] = u;
    }
    __syncthreads();

    float acc[2][8][4];
    #pragma unroll
    for (int i = 0; i < 2; i++)
        #pragma unroll
        for (int j = 0; j < 8; j++)
            #pragma unroll
            for (int k = 0; k < 4; k++) acc[i][j][k] = 0.f;

    #pragma unroll
    for (int s = 0; s < 8; s++) {          // 8 x k16 steps
        const int ko = s * 8;
        unsigned a[2][4];
        #pragma unroll
        for (int mt = 0; mt < 2; mt++) {
            int r = wm + mt * 16 + g;
            a[mt][0] = As[r * ASH + ko + c];
            a[mt][1] = As[(r + 8) * ASH + ko + c];
            a[mt][2] = As[r * ASH + ko + c + 4];
            a[mt][3] = As[(r + 8) * ASH + ko + c + 4];
        }
        #pragma unroll
        for (int nt = 0; nt < 8; nt++) {
            int col = wn + nt * 8 + g;
            unsigned b0 = Bs[col * BSH + ko + c];
            unsigned b1 = Bs[col * BSH + ko + c + 4];
            #pragma unroll
            for (int mt = 0; mt < 2; mt++) {
                asm volatile(
                    "mma.sync.aligned.m16n8k16.row.col.f32.f16.f16.f32 "
                    "{%0,%1,%2,%3}, {%4,%5,%6,%7}, {%8,%9}, {%0,%1,%2,%3};\n"
                    : "+f"(acc[mt][nt][0]), "+f"(acc[mt][nt][1]),
                      "+f"(acc[mt][nt][2]), "+f"(acc[mt][nt][3])
                    : "r"(a[mt][0]), "r"(a[mt][1]), "r"(a[mt][2]), "r"(a[mt][3]),
                      "r"(b0), "r"(b1));
            }
        }
    }

    const int c2 = c * 2;
    #pragma unroll
    for (int nt = 0; nt < 8; nt++) {
        int col = wn + nt * 8 + c2;
        float bi0 = bias[col], bi1 = bias[col + 1];
        #pragma unroll
        for (int mt = 0; mt < 2; mt++) {
            int r = row0 + wm + mt * 16 + g;
            if (r < M) {
                float rs = rowscale ? rowscale[r] : 1.0f;
                float ox = fmaxf(acc[mt][nt][0] + bi0, 0.f) * rs;
                float oy = fmaxf(acc[mt][nt][1] + bi1, 0.f) * rs;
                if (HALF_OUT)
                    ((__half2*)outp)[r * 64 + (col >> 1)] = __floats2half2_rn(ox, oy);
                else
                    ((float2*)outp)[r * 64 + (col >> 1)] = make_float2(ox, oy);
            }
            int r2 = r + 8;
            if (r2 < M) {
                float rs = rowscale ? rowscale[r2] : 1.0f;
                float ox = fmaxf(acc[mt][nt][2] + bi0, 0.f) * rs;
                float oy = fmaxf(acc[mt][nt][3] + bi1, 0.f) * rs;
                if (HALF_OUT)
                    ((__half2*)outp)[r2 * 64 + (col >> 1)] = __floats2half2_rn(ox, oy);
                else
                    ((float2*)outp)[r2 * 64 + (col >> 1)] = make_float2(ox, oy);
            }
        }
    }
}

// ---------------- launch (single stream) ----------------
extern "C" void kernel_launch(void* const* d_in, const int* in_sizes, int n_in,
                              void* d_out, int out_size)
{
    const int*   batch = (const int*)d_in[0];
    const int*   src   = (const int*)d_in[1];
    const int*   dst   = (const int*)d_in[2];
    const float* emb   = (const float*)d_in[3];
    const float* W1    = (const float*)d_in[4];
    const float* b1    = (const float*)d_in[5];
    const float* W2    = (const float*)d_in[6];
    const float* b2    = (const float*)d_in[7];
    const float* W3    = (const float*)d_in[8];
    const float* b3    = (const float*)d_in[9];

    __half2* hbuf;   cudaGetSymbolAddress((void**)&hbuf, g_hh);
    __half2* aggbuf; cudaGetSymbolAddress((void**)&aggbuf, g_agg);
    unsigned* wt;    cudaGetSymbolAddress((void**)&wt, g_wt);
    int* degp;       cudaGetSymbolAddress((void**)&degp, g_deg);
    float* nsrc;     cudaGetSymbolAddress((void**)&nsrc, g_norm_src);

    cudaFuncSetAttribute(k_gemm_f16<true>,
                         cudaFuncAttributeMaxDynamicSharedMemorySize, GEMM_SMEM);
    cudaFuncSetAttribute(k_gemm_f16<false>,
                         cudaFuncAttributeMaxDynamicSharedMemorySize, GEMM_SMEM);

    const int scan_blocks = (NN + 1023) / 1024;   // 49

    cudaMemsetAsync(degp, 0, 2 * NN * sizeof(int), 0);
    k_wconv<<<(3 * 8192 + 255) / 256, 256>>>(W1, W2, W3);
    k_degree<<<(EE / 4 + 255) / 256, 256>>>((const int4*)src, (const int4*)dst);
    k_scan1n<<<scan_blocks, 1024>>>();
    k_h0<<<(NN * 16 + 255) / 256, 256>>>(batch, (const float4*)emb);
    k_scan3<<<(NN + 255) / 256, 256>>>();
    k_fill<<<(EE / 4 + 255) / 256, 256>>>((const int4*)src, (const int4*)dst);

    const int gemm_grid = (NN + 127) / 128;       // 391
    const int spmm_grid = (NN + 7) / 8;

    // layer 1
    k_spmm<<<spmm_grid, 256>>>();
    k_gemm_f16<true><<<gemm_grid, 256, GEMM_SMEM>>>((const uint4*)aggbuf,
                                                    (const uint2*)wt, b1,
                                                    nsrc, hbuf, NN);
    // layer 2
    k_spmm<<<spmm_grid, 256>>>();
    k_gemm_f16<true><<<gemm_grid, 256, GEMM_SMEM>>>((const uint4*)aggbuf,
                                                    (const uint2*)(wt + 8192), b2,
                                                    nsrc, hbuf, NN);
    // layer 3 -> d_out (fp32, no rowscale)
    k_spmm<<<spmm_grid, 256>>>();
    k_gemm_f16<false><<<gemm_grid, 256, GEMM_SMEM>>>((const uint4*)aggbuf,
                                                     (const uint2*)(wt + 16384), b3,
                                                     nullptr, d_out, NN);
}

// round 13
// speedup vs baseline: 2.1011x; 1.0143x over previous
#include <cuda_runtime.h>
#include <cuda_fp16.h>

#define NN 50000
#define EE 800000
#define DD 128

// ---------------- device scratch (no allocs allowed) ----------------
__device__ __half2  g_hh[NN * 64];   // current layer input, fp16, pre-scaled by norm_src
__device__ __half2  g_agg[NN * 64];  // SpMM output, fp16 (already * norm_dst)
__device__ unsigned g_wt[3 * 8192];  // W1..W3 as fp16, n-major: wt[l][n][k] (half2 over k)
__device__ int      g_deg[2 * NN];   // [0,NN)=deg_out, [NN,2NN)=deg_in
__device__ float    g_norm_src[NN];
__device__ float    g_norm_dst[NN];
__device__ int      g_row_ptr[NN + 1];
__device__ int      g_cursor[NN];
__device__ int      g_col[EE];       // src ids grouped by dst
__device__ int      g_bsum[64];

// ---------------- setup 1: wconv (blocks 0..95) + degree (rest), independent ----------------
#define WCONV_BLOCKS 96                       // 3*8192 / 256
#define DEG_BLOCKS   ((EE / 8 + 255) / 256)   // 8 edges per thread

__global__ void k_setup1(const int4* __restrict__ src4, const int4* __restrict__ dst4,
                         const float* __restrict__ W1, const float* __restrict__ W2,
                         const float* __restrict__ W3) {
    int bid = blockIdx.x;
    if (bid < WCONV_BLOCKS) {
        // W[k][n] fp32 -> wt[l][n][k] fp16 (half2 packed over k)
        int idx = bid * 256 + threadIdx.x;     // 0 .. 3*8192-1
        int l   = idx >> 13;
        int rem = idx & 8191;
        int kp  = rem >> 7;
        int n   = rem & 127;
        const float* W = (l == 0) ? W1 : (l == 1) ? W2 : W3;
        __half2 h = __floats2half2_rn(W[(2 * kp) * 128 + n], W[(2 * kp + 1) * 128 + n]);
        g_wt[l * 8192 + n * 64 + kp] = *(unsigned*)&h;
    } else {
        int t = (bid - WCONV_BLOCKS) * 256 + threadIdx.x;   // 8 edges per thread
        if (t < EE / 8) {
            int4 s0 = src4[t * 2],     d0 = dst4[t * 2];
            int4 s1 = src4[t * 2 + 1], d1 = dst4[t * 2 + 1];
            atomicAdd(&g_deg[s0.x], 1); atomicAdd(&g_deg[s0.y], 1);
            atomicAdd(&g_deg[s0.z], 1); atomicAdd(&g_deg[s0.w], 1);
            atomicAdd(&g_deg[s1.x], 1); atomicAdd(&g_deg[s1.y], 1);
            atomicAdd(&g_deg[s1.z], 1); atomicAdd(&g_deg[s1.w], 1);
            atomicAdd(&g_deg[NN + d0.x], 1); atomicAdd(&g_deg[NN + d0.y], 1);
            atomicAdd(&g_deg[NN + d0.z], 1); atomicAdd(&g_deg[NN + d0.w], 1);
            atomicAdd(&g_deg[NN + d1.x], 1); atomicAdd(&g_deg[NN + d1.y], 1);
            atomicAdd(&g_deg[NN + d1.z], 1); atomicAdd(&g_deg[NN + d1.w], 1);
        }
    }
}

// ---------------- scan phase 1 over deg_in (1024/block) + norms (fused) ----------------
__global__ void k_scan1n() {
    __shared__ int warp_sums[32];
    const int tid = threadIdx.x;
    int i = blockIdx.x * 1024 + tid;
    int v = 0;
    if (i < NN) {
        int dout = g_deg[i];      if (dout < 1) dout = 1;
        int din  = g_deg[NN + i];
        v = din;
        if (din < 1) din = 1;
        g_norm_src[i] = rsqrtf((float)dout);
        g_norm_dst[i] = rsqrtf((float)din);
    }
    int x = v;
    #pragma unroll
    for (int off = 1; off < 32; off <<= 1) {
        int y = __shfl_up_sync(0xffffffffu, x, off);
        if ((tid & 31) >= off) x += y;
    }
    if ((tid & 31) == 31) warp_sums[tid >> 5] = x;
    __syncthreads();
    if (tid < 32) {
        int w = warp_sums[tid];
        #pragma unroll
        for (int off = 1; off < 32; off <<= 1) {
            int y = __shfl_up_sync(0xffffffffu, w, off);
            if (tid >= off) w += y;
        }
        warp_sums[tid] = w;
    }
    __syncthreads();
    int warp_off = (tid >= 32) ? warp_sums[(tid >> 5) - 1] : 0;
    int incl = x + warp_off;
    if (i < NN) g_row_ptr[i] = incl - v;       // local exclusive
    if (tid == 1023) g_bsum[blockIdx.x] = incl;
}

// ---------------- setup 2: scan3 (blocks 0..195) + h0 (rest); both depend on scan1n ----------------
#define SCAN3_BLOCKS 196                      // ceil(NN/256)
#define H0_BLOCKS    ((NN * 16 + 255) / 256)  // 3125

__global__ void k_setup2(const int* __restrict__ batch, const float4* __restrict__ emb) {
    int bid = blockIdx.x;
    if (bid < SCAN3_BLOCKS) {
        __shared__ int s_off;
        const int tid = threadIdx.x;
        const int grp = bid >> 2;
        if (tid < 32) {
            int a = (tid < grp)      ? g_bsum[tid]      : 0;
            int b = (tid + 32 < grp) ? g_bsum[tid + 32] : 0;
            int s = a + b;
            #pragma unroll
            for (int off = 16; off > 0; off >>= 1)
                s += __shfl_down_sync(0xffffffffu, s, off);
            if (tid == 0) s_off = s;
        }
        __syncthreads();
        int i = bid * 256 + tid;
        if (i < NN) {
            int val = g_row_ptr[i] + s_off;
            g_row_ptr[i] = val;
            g_cursor[i]  = val;
        }
        if (i == 0) g_row_ptr[NN] = EE;
    } else {
        // h0 = half(emb[batch] * norm_src); 2 float4 per thread
        int idx = (bid - SCAN3_BLOCKS) * 256 + threadIdx.x;
        if (idx >= NN * 16) return;
        int i = idx >> 4, q = idx & 15;
        float ns = g_norm_src[i];
        const float4* row = emb + (size_t)batch[i] * 32;
        float4 v0 = row[q * 2];
        float4 v1 = row[q * 2 + 1];
        __half2 p0 = __floats2half2_rn(v0.x * ns, v0.y * ns);
        __half2 p1 = __floats2half2_rn(v0.z * ns, v0.w * ns);
        __half2 p2 = __floats2half2_rn(v1.x * ns, v1.y * ns);
        __half2 p3 = __floats2half2_rn(v1.z * ns, v1.w * ns);
        uint4 o = make_uint4(*(unsigned*)&p0, *(unsigned*)&p1,
                             *(unsigned*)&p2, *(unsigned*)&p3);
        ((uint4*)g_hh)[idx] = o;
    }
}

// ---------------- fill: 8 edges per thread ----------------
__global__ void k_fill(const int4* __restrict__ src4, const int4* __restrict__ dst4) {
    int t = blockIdx.x * blockDim.x + threadIdx.x;
    if (t < EE / 8) {
        int4 s0 = src4[t * 2],     d0 = dst4[t * 2];
        int4 s1 = src4[t * 2 + 1], d1 = dst4[t * 2 + 1];
        g_col[atomicAdd(&g_cursor[d0.x], 1)] = s0.x;
        g_col[atomicAdd(&g_cursor[d0.y], 1)] = s0.y;
        g_col[atomicAdd(&g_cursor[d0.z], 1)] = s0.z;
        g_col[atomicAdd(&g_cursor[d0.w], 1)] = s0.w;
        g_col[atomicAdd(&g_cursor[d1.x], 1)] = s1.x;
        g_col[atomicAdd(&g_cursor[d1.y], 1)] = s1.y;
        g_col[atomicAdd(&g_cursor[d1.z], 1)] = s1.z;
        g_col[atomicAdd(&g_cursor[d1.w], 1)] = s1.w;
    }
}

// ---------------- SpMM: warp per dst row; 16 lanes x uint4, 2 edges in flight ----------------
__global__ void k_spmm() {
    int warp = (blockIdx.x * blockDim.x + threadIdx.x) >> 5;
    int lane = threadIdx.x & 31;
    if (warp >= NN) return;
    const uint4* hp = (const uint4*)g_hh;      // row stride = 16 uint4 (128 halves)
    const int hl  = lane & 15;
    const int sel = lane >> 4;
    int beg = g_row_ptr[warp];
    int end = g_row_ptr[warp + 1];
    float acc[8];
    #pragma unroll
    for (int k = 0; k < 8; k++) acc[k] = 0.f;

    for (int j0 = beg; j0 < end; j0 += 32) {
        int c = 0;
        if (j0 + lane < end) c = g_col[j0 + lane];
        int n = end - j0; if (n > 32) n = 32;
        int t = 0;
        for (; t + 3 < n; t += 4) {
            int s0 = __shfl_sync(0xffffffffu, c, t + sel);
            int s1 = __shfl_sync(0xffffffffu, c, t + 2 + sel);
            uint4 u0 = hp[s0 * 16 + hl];
            uint4 u1 = hp[s1 * 16 + hl];
            float2 f;
            f = __half22float2(*(__half2*)&u0.x); acc[0] += f.x; acc[1] += f.y;
            f = __half22float2(*(__half2*)&u0.y); acc[2] += f.x; acc[3] += f.y;
            f = __half22float2(*(__half2*)&u0.z); acc[4] += f.x; acc[5] += f.y;
            f = __half22float2(*(__half2*)&u0.w); acc[6] += f.x; acc[7] += f.y;
            f = __half22float2(*(__half2*)&u1.x); acc[0] += f.x; acc[1] += f.y;
            f = __half22float2(*(__half2*)&u1.y); acc[2] += f.x; acc[3] += f.y;
            f = __half22float2(*(__half2*)&u1.z); acc[4] += f.x; acc[5] += f.y;
            f = __half22float2(*(__half2*)&u1.w); acc[6] += f.x; acc[7] += f.y;
        }
        for (; t < n; t += 2) {
            int e = t + sel;
            int s = __shfl_sync(0xffffffffu, c, e < 31 ? e : 31);
            if (e < n) {
                uint4 u = hp[s * 16 + hl];
                float2 f;
                f = __half22float2(*(__half2*)&u.x); acc[0] += f.x; acc[1] += f.y;
                f = __half22float2(*(__half2*)&u.y); acc[2] += f.x; acc[3] += f.y;
                f = __half22float2(*(__half2*)&u.z); acc[4] += f.x; acc[5] += f.y;
                f = __half22float2(*(__half2*)&u.w); acc[6] += f.x; acc[7] += f.y;
            }
        }
    }
    #pragma unroll
    for (int k = 0; k < 8; k++) acc[k] += __shfl_xor_sync(0xffffffffu, acc[k], 16);

    if (sel == 0) {
        float nd = g_norm_dst[warp];
        __half2 p0 = __floats2half2_rn(acc[0] * nd, acc[1] * nd);
        __half2 p1 = __floats2half2_rn(acc[2] * nd, acc[3] * nd);
        __half2 p2 = __floats2half2_rn(acc[4] * nd, acc[5] * nd);
        __half2 p3 = __floats2half2_rn(acc[6] * nd, acc[7] * nd);
        uint4 o = make_uint4(*(unsigned*)&p0, *(unsigned*)&p1,
                             *(unsigned*)&p2, *(unsigned*)&p3);
        ((uint4*)g_agg)[warp * 16 + hl] = o;
    }
}

// ---------------- FP16 tensor-core GEMM: out = relu(A @ W + b) [* rowscale] ----------------
#define ASH 68   // half2 per A smem row
#define BSH 66   // half2 per B smem row
#define GEMM_SMEM ((128 * ASH + 128 * BSH) * 4)   // 68608 B

template <bool HALF_OUT>
__global__ __launch_bounds__(256, 2) void k_gemm_f16(
    const uint4* __restrict__ A4, const uint2* __restrict__ WT2,
    const float* __restrict__ bias, const float* __restrict__ rowscale,
    void* __restrict__ outp, int M)
{
    extern __shared__ unsigned smem[];
    unsigned* As = smem;                  // [128][ASH] half2
    unsigned* Bs = smem + 128 * ASH;      // [128][BSH] half2, n-major

    const int tid  = threadIdx.x;
    const int wid  = tid >> 5;
    const int lane = tid & 31;
    const int g = lane >> 2;
    const int c = lane & 3;
    const int wm = (wid & 3) * 32;
    const int wn = (wid >> 2) * 64;
    const int row0 = blockIdx.x * 128;

    #pragma unroll
    for (int l = 0; l < 8; l++) {
        int idx = l * 256 + tid;
        int r = idx >> 4;
        int q = idx & 15;
        uint4 u = make_uint4(0u, 0u, 0u, 0u);
        if (row0 + r < M) u = A4[(row0 + r) * 16 + q];
        *(uint4*)&As[r * ASH + q * 4] = u;
    }
    #pragma unroll
    for (int l = 0; l < 16; l++) {
        int idx = l * 256 + tid;
        int n = idx >> 5;
        int q = idx & 31;
        uint2 u = WT2[n * 32 + q];
        *(uint2*)&Bs[n * BSH + q * 2] = u;
    }
    __syncthreads();

    float acc[2][8][4];
    #pragma unroll
    for (int i = 0; i < 2; i++)
        #pragma unroll
        for (int j = 0; j < 8; j++)
            #pragma unroll
            for (int k = 0; k < 4; k++) acc[i][j][k] = 0.f;

    #pragma unroll
    for (int s = 0; s < 8; s++) {
        const int ko = s * 8;
        unsigned a[2][4];
        #pragma unroll
        for (int mt = 0; mt < 2; mt++) {
            int r = wm + mt * 16 + g;
            a[mt][0] = As[r * ASH + ko + c];
            a[mt][1] = As[(r + 8) * ASH + ko + c];
            a[mt][2] = As[r * ASH + ko + c + 4];
            a[mt][3] = As[(r + 8) * ASH + ko + c + 4];
        }
        #pragma unroll
        for (int nt = 0; nt < 8; nt++) {
            int col = wn + nt * 8 + g;
            unsigned b0 = Bs[col * BSH + ko + c];
            unsigned b1 = Bs[col * BSH + ko + c + 4];
            #pragma unroll
            for (int mt = 0; mt < 2; mt++) {
                asm volatile(
                    "mma.sync.aligned.m16n8k16.row.col.f32.f16.f16.f32 "
                    "{%0,%1,%2,%3}, {%4,%5,%6,%7}, {%8,%9}, {%0,%1,%2,%3};\n"
                    : "+f"(acc[mt][nt][0]), "+f"(acc[mt][nt][1]),
                      "+f"(acc[mt][nt][2]), "+f"(acc[mt][nt][3])
                    : "r"(a[mt][0]), "r"(a[mt][1]), "r"(a[mt][2]), "r"(a[mt][3]),
                      "r"(b0), "r"(b1));
            }
        }
    }

    const int c2 = c * 2;
    #pragma unroll
    for (int nt = 0; nt < 8; nt++) {
        int col = wn + nt * 8 + c2;
        float bi0 = bias[col], bi1 = bias[col + 1];
        #pragma unroll
        for (int mt = 0; mt < 2; mt++) {
            int r = row0 + wm + mt * 16 + g;
            if (r < M) {
                float rs = rowscale ? rowscale[r] : 1.0f;
                float ox = fmaxf(acc[mt][nt][0] + bi0, 0.f) * rs;
                float oy = fmaxf(acc[mt][nt][1] + bi1, 0.f) * rs;
                if (HALF_OUT)
                    ((__half2*)outp)[r * 64 + (col >> 1)] = __floats2half2_rn(ox, oy);
                else
                    ((float2*)outp)[r * 64 + (col >> 1)] = make_float2(ox, oy);
            }
            int r2 = r + 8;
            if (r2 < M) {
                float rs = rowscale ? rowscale[r2] : 1.0f;
                float ox = fmaxf(acc[mt][nt][2] + bi0, 0.f) * rs;
                float oy = fmaxf(acc[mt][nt][3] + bi1, 0.f) * rs;
                if (HALF_OUT)
                    ((__half2*)outp)[r2 * 64 + (col >> 1)] = __floats2half2_rn(ox, oy);
                else
                    ((float2*)outp)[r2 * 64 + (col >> 1)] = make_float2(ox, oy);
            }
        }
    }
}

// ---------------- launch (single stream) ----------------
extern "C" void kernel_launch(void* const* d_in, const int* in_sizes, int n_in,
                              void* d_out, int out_size)
{
    const int*   batch = (const int*)d_in[0];
    const int*   src   = (const int*)d_in[1];
    const int*   dst   = (const int*)d_in[2];
    const float* emb   = (const float*)d_in[3];
    const float* W1    = (const float*)d_in[4];
    const float* b1    = (const float*)d_in[5];
    const float* W2    = (const float*)d_in[6];
    const float* b2    = (const float*)d_in[7];
    const float* W3    = (const float*)d_in[8];
    const float* b3    = (const float*)d_in[9];

    __half2* hbuf;   cudaGetSymbolAddress((void**)&hbuf, g_hh);
    __half2* aggbuf; cudaGetSymbolAddress((void**)&aggbuf, g_agg);
    unsigned* wt;    cudaGetSymbolAddress((void**)&wt, g_wt);
    int* degp;       cudaGetSymbolAddress((void**)&degp, g_deg);
    float* nsrc;     cudaGetSymbolAddress((void**)&nsrc, g_norm_src);

    cudaFuncSetAttribute(k_gemm_f16<true>,
                         cudaFuncAttributeMaxDynamicSharedMemorySize, GEMM_SMEM);
    cudaFuncSetAttribute(k_gemm_f16<false>,
                         cudaFuncAttributeMaxDynamicSharedMemorySize, GEMM_SMEM);

    const int scan_blocks = (NN + 1023) / 1024;   // 49

    cudaMemsetAsync(degp, 0, 2 * NN * sizeof(int), 0);
    k_setup1<<<WCONV_BLOCKS + DEG_BLOCKS, 256>>>((const int4*)src, (const int4*)dst,
                                                 W1, W2, W3);
    k_scan1n<<<scan_blocks, 1024>>>();
    k_setup2<<<SCAN3_BLOCKS + H0_BLOCKS, 256>>>(batch, (const float4*)emb);
    k_fill<<<(EE / 8 + 255) / 256, 256>>>((const int4*)src, (const int4*)dst);

    const int gemm_grid = (NN + 127) / 128;       // 391
    const int spmm_grid = (NN + 7) / 8;

    // layer 1
    k_spmm<<<spmm_grid, 256>>>();
    k_gemm_f16<true><<<gemm_grid, 256, GEMM_SMEM>>>((const uint4*)aggbuf,
                                                    (const uint2*)wt, b1,
                                                    nsrc, hbuf, NN);
    // layer 2
    k_spmm<<<spmm_grid, 256>>>();
    k_gemm_f16<true><<<gemm_grid, 256, GEMM_SMEM>>>((const uint4*)aggbuf,
                                                    (const uint2*)(wt + 8192), b2,
                                                    nsrc, hbuf, NN);
    // layer 3 -> d_out (fp32, no rowscale)
    k_spmm<<<spmm_grid, 256>>>();
    k_gemm_f16<false><<<gemm_grid, 256, GEMM_SMEM>>>((const uint4*)aggbuf,
                                                     (const uint2*)(wt + 16384), b3,
                                                     nullptr, d_out, NN);
}